// round 5
// baseline (speedup 1.0000x reference)
#include <cuda_runtime.h>
#include <cuda_fp16.h>
#include <cstdint>
#include <cstddef>

#define TB 256
#define BATCH 256
#define TENC 200
#define TD 200
#define DMODEL 256
#define INR 400
#define PM_ROWS 16
#define PM_BLOCKS (BATCH * TENC / PM_ROWS)   // 3200

// ------------------------- persistent device scratch -------------------------
__device__ float g_pm[BATCH * TENC * DMODEL];   // processed_memory (52 MB fp32)

// fp16 weights, TRANSPOSED [K][O_pad] (outputs contiguous -> coalesced)
__device__ __align__(16) __half g_tWp1[400 * 256];
__device__ __align__(16) __half g_tWp2[256 * 128];
__device__ __align__(16) __half g_tWaih[384 * 768];
__device__ __align__(16) __half g_tWahh[256 * 768];
__device__ __align__(16) __half g_tWq[256 * 256];
__device__ __align__(16) __half g_tWproj[512 * 256];
__device__ __align__(16) __half g_tWd1i[256 * 768];
__device__ __align__(16) __half g_tWd1h[256 * 768];
__device__ __align__(16) __half g_tWd2i[256 * 768];
__device__ __align__(16) __half g_tWd2h[256 * 768];
__device__ __align__(16) __half g_tWmel[256 * 512];   // O padded 400->512

// ------------------------- helpers -------------------------
__device__ __forceinline__ float tanh_approx(float x) {
    float y;
    asm("tanh.approx.f32 %0, %1;" : "=f"(y) : "f"(x));
    return y;
}
__device__ __forceinline__ float sigmoidf_(float x) {
    return 1.0f / (1.0f + __expf(-x));
}

__device__ __forceinline__ unsigned long long f2pack(float x, float y) {
    unsigned long long d;
    asm("mov.b64 %0, {%1, %2};" : "=l"(d) : "f"(x), "f"(y));
    return d;
}
__device__ __forceinline__ float2 f2unpack(unsigned long long v) {
    float2 r;
    asm("mov.b64 {%0, %1}, %2;" : "=f"(r.x), "=f"(r.y) : "l"(v));
    return r;
}
__device__ __forceinline__ unsigned long long ffma2(unsigned long long a,
                                                    unsigned long long b,
                                                    unsigned long long c) {
    unsigned long long d;
    asm("fma.rn.f32x2 %0, %1, %2, %3;" : "=l"(d) : "l"(a), "l"(b), "l"(c));
    return d;
}

// ------------------------- prep kernel: pm + transpose-convert ---------------
struct PrepArgs {
    const float* src[11];
    __half* dst[11];
    int O[11], K[11], OP[11];
    int start[12];           // cumulative block offsets for transpose section
    const float* enc;
    const float* memW;       // fp32 mem_W [256,256]
    float* pm;
};

__global__ void __launch_bounds__(TB) prep_kernel(PrepArgs a) {
    int bid = blockIdx.x;
    if (bid < PM_BLOCKS) {
        // processed_memory: pm[row][o] = dot(memW[o][:], enc[row][:])
        __shared__ __align__(16) float se[PM_ROWS][DMODEL];
        size_t row0 = (size_t)bid * PM_ROWS;
        for (int i = threadIdx.x; i < PM_ROWS * DMODEL; i += TB)
            se[i >> 8][i & 255] = a.enc[row0 * DMODEL + i];
        __syncthreads();
        int o = threadIdx.x;
        float acc[PM_ROWS];
#pragma unroll
        for (int r = 0; r < PM_ROWS; ++r) acc[r] = 0.f;
        const float4* W4 = reinterpret_cast<const float4*>(a.memW + (size_t)o * DMODEL);
#pragma unroll 4
        for (int k4 = 0; k4 < DMODEL / 4; ++k4) {
            float4 w = __ldg(&W4[k4]);
#pragma unroll
            for (int r = 0; r < PM_ROWS; ++r) {
                const float* e = &se[r][k4 * 4];
                float s = acc[r];
                s = fmaf(w.x, e[0], s); s = fmaf(w.y, e[1], s);
                s = fmaf(w.z, e[2], s); s = fmaf(w.w, e[3], s);
                acc[r] = s;
            }
        }
#pragma unroll
        for (int r = 0; r < PM_ROWS; ++r)
            a.pm[(row0 + r) * DMODEL + o] = acc[r];
        return;
    }
    // transpose-convert section: src [O][K] fp32 -> dst [K][OP] fp16 (pad w/ 0)
    int tb = bid - PM_BLOCKS;
    int m = 0;
#pragma unroll
    for (int j = 0; j < 11; ++j)
        if (tb >= a.start[j + 1]) m = j + 1;
    int local = (tb - a.start[m]) * TB + threadIdx.x;
    int OP = a.OP[m], O = a.O[m], K = a.K[m];
    int k = local / OP, o = local - k * OP;
    __half v = (o < O) ? __float2half_rn(a.src[m][(size_t)o * K + k]) : __half(0.f);
    a.dst[m][local] = v;
}

// ------------------------- gemv engine -------------------------------------
// WT: fp16 [K][Ostride]; x2: float2[K] = (row0,row1); part: float2[NTILE*8*256]
// Task (ot, kc): warp computes partial over k-chunk kc for o-tile ot.
template <int K, int NTILE, int VEC>
__device__ __forceinline__ void gemvT(const __half* __restrict__ WT, int Ostride,
                                      const float2* __restrict__ x2,
                                      float2* __restrict__ part) {
    const int lane = threadIdx.x & 31;
    const int w = threadIdx.x >> 5;
    constexpr int CH = K / 8;
#pragma unroll
    for (int task = w; task < NTILE * 8; task += 8) {
        const int ot = task >> 3, kc = task & 7;
        const __half* base = WT + (size_t)(kc * CH) * Ostride + ot * 256 + lane * VEC;
        const float2* xp = x2 + kc * CH;
        // acc0[p] = (y_{2p}, y_{2p+1}) for row0 ; acc1[p] same for row1
        unsigned long long acc0[VEC / 2], acc1[VEC / 2];
#pragma unroll
        for (int j = 0; j < VEC / 2; ++j) { acc0[j] = 0ull; acc1[j] = 0ull; }
#pragma unroll 4
        for (int kk = 0; kk < CH; ++kk) {
            float2 xv = xp[kk];
            unsigned long long xx0 = f2pack(xv.x, xv.x);
            unsigned long long xx1 = f2pack(xv.y, xv.y);
            if constexpr (VEC == 8) {
                uint4 wv = __ldg(reinterpret_cast<const uint4*>(base + (size_t)kk * Ostride));
                unsigned int ws[4] = {wv.x, wv.y, wv.z, wv.w};
#pragma unroll
                for (int p = 0; p < 4; ++p) {
                    float2 f = __half22float2(*reinterpret_cast<__half2*>(&ws[p]));
                    unsigned long long wp = f2pack(f.x, f.y);
                    acc0[p] = ffma2(wp, xx0, acc0[p]);
                    acc1[p] = ffma2(wp, xx1, acc1[p]);
                }
            } else {
                uint2 wv = __ldg(reinterpret_cast<const uint2*>(base + (size_t)kk * Ostride));
                unsigned int ws[2] = {wv.x, wv.y};
#pragma unroll
                for (int p = 0; p < 2; ++p) {
                    float2 f = __half22float2(*reinterpret_cast<__half2*>(&ws[p]));
                    unsigned long long wp = f2pack(f.x, f.y);
                    acc0[p] = ffma2(wp, xx0, acc0[p]);
                    acc1[p] = ffma2(wp, xx1, acc1[p]);
                }
            }
        }
        float2* pp = part + task * 256 + lane * VEC;
#pragma unroll
        for (int p = 0; p < VEC / 2; ++p) {
            float2 r0 = f2unpack(acc0[p]);   // (y_{2p} row0, y_{2p+1} row0)
            float2 r1 = f2unpack(acc1[p]);
            pp[2 * p]     = make_float2(r0.x, r1.x);
            pp[2 * p + 1] = make_float2(r0.y, r1.y);
        }
    }
}

__device__ __forceinline__ float2 rsum8(const float2* __restrict__ p, int o) {
    float2 s = p[o];
#pragma unroll
    for (int kc = 1; kc < 8; ++kc) {
        float2 t = p[kc * 256 + o];
        s.x += t.x; s.y += t.y;
    }
    return s;
}

// ------------------------- shared memory layout ----------------------------
struct __align__(16) SD {
    float2 part[6 * 8 * 256];   // 98304 B (partials; also ctx scratch)
    float2 in2[400];
    float2 p12[256];
    float2 x2[384];             // [0:128)=prenet2, [128:384)=ctx
    float2 ah2[256];
    float2 h12[256];
    float2 h22[256];
    float2 d2[256];
    float2 cat2[512];
    float qr[2][256];
    float sc[2][TENC];
    float v[256];
    float b_p1[256]; float b_p2[128];
    float b_aih[768]; float b_ahh[768];
    float b_proj[256];
    float b_d1i[768]; float b_d1h[768];
    float b_d2i[768]; float b_d2h[768];
    float b_mel[400];
};

// ------------------------- main persistent decoder -------------------------
__global__ void __launch_bounds__(TB) decoder_kernel(
    const float* __restrict__ enc, const float* __restrict__ inputs,
    const int* __restrict__ memlen,
    const float* __restrict__ gb_p1, const float* __restrict__ gb_p2,
    const float* __restrict__ gb_aih, const float* __restrict__ gb_ahh,
    const float* __restrict__ vW,
    const float* __restrict__ gb_proj,
    const float* __restrict__ gb_d1i, const float* __restrict__ gb_d1h,
    const float* __restrict__ gb_d2i, const float* __restrict__ gb_d2h,
    const float* __restrict__ gb_mel,
    float* __restrict__ out, int write_align) {
    extern __shared__ unsigned char smem_raw[];
    SD* s = reinterpret_cast<SD*>(smem_raw);

    const int tid = threadIdx.x;
    const int b0 = blockIdx.x * 2;
    const int len0 = memlen[b0];
    const int len1 = memlen[b0 + 1];

    // init state + preload biases/v
    {
        float2 z2 = make_float2(0.f, 0.f);
        s->ah2[tid] = z2; s->h12[tid] = z2; s->h22[tid] = z2;
        s->x2[128 + tid] = z2;
        s->v[tid] = vW[tid];
        s->b_p1[tid] = gb_p1[tid];
        if (tid < 128) s->b_p2[tid] = gb_p2[tid];
        for (int i = tid; i < 768; i += TB) {
            s->b_aih[i] = gb_aih[i]; s->b_ahh[i] = gb_ahh[i];
            s->b_d1i[i] = gb_d1i[i]; s->b_d1h[i] = gb_d1h[i];
            s->b_d2i[i] = gb_d2i[i]; s->b_d2h[i] = gb_d2h[i];
        }
        s->b_proj[tid] = gb_proj[tid];
        for (int i = tid; i < 400; i += TB) s->b_mel[i] = gb_mel[i];
    }
    __syncthreads();

    float* outMel = out;
    float* outAl = out + (size_t)BATCH * TD * INR;

    for (int t = 0; t < TD; ++t) {
        // ---- teacher-forced input ----
        if (t == 0) {
            for (int i = tid; i < INR; i += TB) s->in2[i] = make_float2(0.f, 0.f);
        } else {
            const float* p0 = inputs + ((size_t)b0 * 1000 + (size_t)(t - 1) * 5) * 80;
            const float* p1 = inputs + ((size_t)(b0 + 1) * 1000 + (size_t)(t - 1) * 5) * 80;
            for (int i = tid; i < INR; i += TB)
                s->in2[i] = make_float2(p0[i], p1[i]);
        }
        __syncthreads();

        // ---- prenet 1 (O=256, K=400) ----
        gemvT<400, 1, 8>(g_tWp1, 256, s->in2, s->part);
        __syncthreads();
        {
            float2 r = rsum8(s->part, tid);
            float b = s->b_p1[tid];
            s->p12[tid] = make_float2(fmaxf(r.x + b, 0.f), fmaxf(r.y + b, 0.f));
        }
        __syncthreads();

        // ---- prenet 2 (O=128, K=256) ----
        gemvT<256, 1, 4>(g_tWp2, 128, s->p12, s->part);
        __syncthreads();
        if (tid < 128) {
            float2 r = rsum8(s->part, tid);
            float b = s->b_p2[tid];
            s->x2[tid] = make_float2(fmaxf(r.x + b, 0.f), fmaxf(r.y + b, 0.f));
        }
        __syncthreads();

        // ---- attention GRU ----
        gemvT<384, 3, 8>(g_tWaih, 768, s->x2, s->part);
        gemvT<256, 3, 8>(g_tWahh, 768, s->ah2, s->part + 6144);
        __syncthreads();
        {
            int o = tid;
            const float2* gi = s->part;
            const float2* gh = s->part + 6144;
            float2 ir = rsum8(gi, o), iz = rsum8(gi + 2048, o), inn = rsum8(gi + 4096, o);
            float2 hr = rsum8(gh, o), hz = rsum8(gh + 2048, o), hn = rsum8(gh + 4096, o);
            float bir = s->b_aih[o], biz = s->b_aih[256 + o], bin = s->b_aih[512 + o];
            float bhr = s->b_ahh[o], bhz = s->b_ahh[256 + o], bhn = s->b_ahh[512 + o];
            float2 hp = s->ah2[o];
            float r0 = sigmoidf_(ir.x + bir + hr.x + bhr);
            float z0 = sigmoidf_(iz.x + biz + hz.x + bhz);
            float n0 = tanhf(inn.x + bin + r0 * (hn.x + bhn));
            float h0 = (1.f - z0) * n0 + z0 * hp.x;
            float r1 = sigmoidf_(ir.y + bir + hr.y + bhr);
            float z1 = sigmoidf_(iz.y + biz + hz.y + bhz);
            float n1 = tanhf(inn.y + bin + r1 * (hn.y + bhn));
            float h1 = (1.f - z1) * n1 + z1 * hp.y;
            float2 h = make_float2(h0, h1);
            s->ah2[o] = h;
            s->cat2[o] = h;
        }
        __syncthreads();

        // ---- query projection (O=256, K=256, no bias) ----
        gemvT<256, 1, 8>(g_tWq, 256, s->ah2, s->part);
        __syncthreads();
        {
            float2 r = rsum8(s->part, tid);
            s->qr[0][tid] = r.x;
            s->qr[1][tid] = r.y;
        }
        __syncthreads();

        // ---- Bahdanau scores ----
        {
            int wid = tid >> 5, lane = tid & 31;
            for (int task = wid; task < 2 * TENC; task += 8) {
                int r = task & 1, tt = task >> 1;
                const float4* P = reinterpret_cast<const float4*>(
                    g_pm + ((size_t)(b0 + r) * TENC + tt) * DMODEL);
                const float4* Q = reinterpret_cast<const float4*>(s->qr[r]);
                const float4* V = reinterpret_cast<const float4*>(s->v);
                float acc = 0.f;
#pragma unroll
                for (int u = 0; u < 2; ++u) {
                    int k4 = u * 32 + lane;
                    float4 p = __ldg(&P[k4]);
                    float4 q = Q[k4], v = V[k4];
                    acc += v.x * tanh_approx(p.x + q.x);
                    acc += v.y * tanh_approx(p.y + q.y);
                    acc += v.z * tanh_approx(p.z + q.z);
                    acc += v.w * tanh_approx(p.w + q.w);
                }
#pragma unroll
                for (int sh = 16; sh; sh >>= 1) acc += __shfl_xor_sync(0xffffffffu, acc, sh);
                if (lane == 0) {
                    int L = r ? len1 : len0;
                    s->sc[r][tt] = (tt < L) ? acc : -1e9f;
                }
            }
        }
        __syncthreads();

        // ---- softmax + alignment output ----
        {
            int wid = tid >> 5, lane = tid & 31;
            if (wid < 2) {
                int r = wid;
                float m = -1e30f;
                for (int i = lane; i < TENC; i += 32) m = fmaxf(m, s->sc[r][i]);
#pragma unroll
                for (int sh = 16; sh; sh >>= 1) m = fmaxf(m, __shfl_xor_sync(0xffffffffu, m, sh));
                float sum = 0.f;
                for (int i = lane; i < TENC; i += 32) {
                    float e = __expf(s->sc[r][i] - m);
                    s->sc[r][i] = e;
                    sum += e;
                }
#pragma unroll
                for (int sh = 16; sh; sh >>= 1) sum += __shfl_xor_sync(0xffffffffu, sum, sh);
                float inv = 1.f / sum;
                float* ao = outAl + ((size_t)(b0 + r) * TD + t) * TENC;
                for (int i = lane; i < TENC; i += 32) {
                    float a = s->sc[r][i] * inv;
                    s->sc[r][i] = a;
                    if (write_align) ao[i] = a;
                }
            }
        }
        __syncthreads();

        // ---- attention context ----
        {
            float* scr = reinterpret_cast<float*>(s->part);
            int g = tid & 63, row = (tid >> 6) & 1, th = tid >> 7;
            const float4* E = reinterpret_cast<const float4*>(
                                  enc + (size_t)(b0 + row) * TENC * DMODEL) + g;
            const float* sc = s->sc[row];
            float4 acc = make_float4(0.f, 0.f, 0.f, 0.f);
            int tt0 = th * 100;
#pragma unroll 4
            for (int tt = tt0; tt < tt0 + 100; ++tt) {
                float a = sc[tt];
                float4 e = __ldg(&E[(size_t)tt * 64]);
                acc.x = fmaf(a, e.x, acc.x);
                acc.y = fmaf(a, e.y, acc.y);
                acc.z = fmaf(a, e.z, acc.z);
                acc.w = fmaf(a, e.w, acc.w);
            }
            reinterpret_cast<float4*>(scr + (row * 2 + th) * 256)[g] = acc;
        }
        __syncthreads();
        {
            const float* scr = reinterpret_cast<const float*>(s->part);
            int o = tid;
            float c0 = scr[o] + scr[256 + o];
            float c1 = scr[512 + o] + scr[768 + o];
            float2 c = make_float2(c0, c1);
            s->x2[128 + o] = c;
            s->cat2[256 + o] = c;
        }
        __syncthreads();

        // ---- project to decoder input (O=256, K=512) ----
        gemvT<512, 1, 8>(g_tWproj, 256, s->cat2, s->part);
        __syncthreads();
        {
            float2 r = rsum8(s->part, tid);
            float b = s->b_proj[tid];
            s->d2[tid] = make_float2(r.x + b, r.y + b);
        }
        __syncthreads();

        // ---- decoder GRU 1 (+residual) ----
        gemvT<256, 3, 8>(g_tWd1i, 768, s->d2, s->part);
        gemvT<256, 3, 8>(g_tWd1h, 768, s->h12, s->part + 6144);
        __syncthreads();
        {
            int o = tid;
            const float2* gi = s->part;
            const float2* gh = s->part + 6144;
            float2 ir = rsum8(gi, o), iz = rsum8(gi + 2048, o), inn = rsum8(gi + 4096, o);
            float2 hr = rsum8(gh, o), hz = rsum8(gh + 2048, o), hn = rsum8(gh + 4096, o);
            float bir = s->b_d1i[o], biz = s->b_d1i[256 + o], bin = s->b_d1i[512 + o];
            float bhr = s->b_d1h[o], bhz = s->b_d1h[256 + o], bhn = s->b_d1h[512 + o];
            float2 hp = s->h12[o];
            float r0 = sigmoidf_(ir.x + bir + hr.x + bhr);
            float z0 = sigmoidf_(iz.x + biz + hz.x + bhz);
            float n0 = tanhf(inn.x + bin + r0 * (hn.x + bhn));
            float h0 = (1.f - z0) * n0 + z0 * hp.x;
            float r1 = sigmoidf_(ir.y + bir + hr.y + bhr);
            float z1 = sigmoidf_(iz.y + biz + hz.y + bhz);
            float n1 = tanhf(inn.y + bin + r1 * (hn.y + bhn));
            float h1 = (1.f - z1) * n1 + z1 * hp.y;
            s->h12[o] = make_float2(h0, h1);
            float2 d = s->d2[o];
            s->d2[o] = make_float2(d.x + h0, d.y + h1);
        }
        __syncthreads();

        // ---- decoder GRU 2 (+residual) ----
        gemvT<256, 3, 8>(g_tWd2i, 768, s->d2, s->part);
        gemvT<256, 3, 8>(g_tWd2h, 768, s->h22, s->part + 6144);
        __syncthreads();
        {
            int o = tid;
            const float2* gi = s->part;
            const float2* gh = s->part + 6144;
            float2 ir = rsum8(gi, o), iz = rsum8(gi + 2048, o), inn = rsum8(gi + 4096, o);
            float2 hr = rsum8(gh, o), hz = rsum8(gh + 2048, o), hn = rsum8(gh + 4096, o);
            float bir = s->b_d2i[o], biz = s->b_d2i[256 + o], bin = s->b_d2i[512 + o];
            float bhr = s->b_d2h[o], bhz = s->b_d2h[256 + o], bhn = s->b_d2h[512 + o];
            float2 hp = s->h22[o];
            float r0 = sigmoidf_(ir.x + bir + hr.x + bhr);
            float z0 = sigmoidf_(iz.x + biz + hz.x + bhz);
            float n0 = tanhf(inn.x + bin + r0 * (hn.x + bhn));
            float h0 = (1.f - z0) * n0 + z0 * hp.x;
            float r1 = sigmoidf_(ir.y + bir + hr.y + bhr);
            float z1 = sigmoidf_(iz.y + biz + hz.y + bhz);
            float n1 = tanhf(inn.y + bin + r1 * (hn.y + bhn));
            float h1 = (1.f - z1) * n1 + z1 * hp.y;
            s->h22[o] = make_float2(h0, h1);
            float2 d = s->d2[o];
            s->d2[o] = make_float2(d.x + h0, d.y + h1);
        }
        __syncthreads();

        // ---- mel projection (O=400 padded to 512, K=256) ----
        gemvT<256, 2, 8>(g_tWmel, 512, s->d2, s->part);
        __syncthreads();
        {
            float* o0 = outMel + ((size_t)b0 * TD + t) * INR;
            float* o1 = outMel + ((size_t)(b0 + 1) * TD + t) * INR;
            for (int o = tid; o < INR; o += TB) {
                int tile = o >> 8, idx = o & 255;
                float2 r = rsum8(s->part + tile * 2048, idx);
                float b = s->b_mel[o];
                o0[o] = r.x + b;
                o1[o] = r.y + b;
            }
        }
        __syncthreads();
    }
}

// ------------------------- launch -------------------------
extern "C" void kernel_launch(void* const* d_in, const int* in_sizes, int n_in,
                              void* d_out, int out_size) {
    const float* enc = (const float*)d_in[0];
    const float* inputs = (const float*)d_in[1];
    const int* memlen = (const int*)d_in[2];

    PrepArgs a;
    static const int srcIdx[11] = {3, 5, 7, 9, 12, 14, 16, 18, 20, 22, 24};
    static const int Oarr[11] = {256, 128, 768, 768, 256, 256, 768, 768, 768, 768, 400};
    static const int Karr[11] = {400, 256, 384, 256, 256, 512, 256, 256, 256, 256, 256};
    static const int OParr[11] = {256, 128, 768, 768, 256, 256, 768, 768, 768, 768, 512};

    void* dsts[11];
    cudaGetSymbolAddress(&dsts[0], g_tWp1);
    cudaGetSymbolAddress(&dsts[1], g_tWp2);
    cudaGetSymbolAddress(&dsts[2], g_tWaih);
    cudaGetSymbolAddress(&dsts[3], g_tWahh);
    cudaGetSymbolAddress(&dsts[4], g_tWq);
    cudaGetSymbolAddress(&dsts[5], g_tWproj);
    cudaGetSymbolAddress(&dsts[6], g_tWd1i);
    cudaGetSymbolAddress(&dsts[7], g_tWd1h);
    cudaGetSymbolAddress(&dsts[8], g_tWd2i);
    cudaGetSymbolAddress(&dsts[9], g_tWd2h);
    cudaGetSymbolAddress(&dsts[10], g_tWmel);

    int cum = 0;
    for (int m = 0; m < 11; ++m) {
        a.src[m] = (const float*)d_in[srcIdx[m]];
        a.dst[m] = (__half*)dsts[m];
        a.O[m] = Oarr[m]; a.K[m] = Karr[m]; a.OP[m] = OParr[m];
        a.start[m] = cum;
        cum += (Karr[m] * OParr[m]) / TB;
    }
    a.start[11] = cum;   // 6800
    a.enc = enc;
    a.memW = (const float*)d_in[11];
    cudaGetSymbolAddress((void**)&a.pm, g_pm);

    prep_kernel<<<PM_BLOCKS + cum, TB>>>(a);

    static bool attr_done = false;
    if (!attr_done) {
        cudaFuncSetAttribute(decoder_kernel,
                             cudaFuncAttributeMaxDynamicSharedMemorySize,
                             (int)sizeof(SD));
        attr_done = true;
    }

    int write_align = (out_size >= BATCH * TD * (INR + TENC)) ? 1 : 0;

    decoder_kernel<<<BATCH / 2, TB, sizeof(SD)>>>(
        enc, inputs, memlen,
        (const float*)d_in[4], (const float*)d_in[6],
        (const float*)d_in[8], (const float*)d_in[10],
        (const float*)d_in[13],
        (const float*)d_in[15],
        (const float*)d_in[17], (const float*)d_in[19],
        (const float*)d_in[21], (const float*)d_in[23],
        (const float*)d_in[25],
        (float*)d_out, write_align);
}

// round 6
// speedup vs baseline: 2.4034x; 2.4034x over previous
#include <cuda_runtime.h>
#include <cuda_fp16.h>
#include <cstdint>
#include <cstddef>

#define TB 1024
#define PREP_TB 256
#define BATCH 256
#define ROWS 4
#define NGROUPS (BATCH / ROWS)   // 64 CTAs
#define TENC 200
#define TD 200
#define DMODEL 256
#define INR 400
#define PM_ROWS 16
#define PM_BLOCKS (BATCH * TENC / PM_ROWS)   // 3200

// ------------------------- persistent device scratch -------------------------
__device__ float g_pm[BATCH * TENC * DMODEL];   // processed_memory (52 MB fp32)

// fp16 weights, TRANSPOSED [K][O_pad] (outputs contiguous -> coalesced)
__device__ __align__(16) __half g_tWp1[400 * 256];
__device__ __align__(16) __half g_tWp2[256 * 128];
__device__ __align__(16) __half g_tWaih[384 * 768];
__device__ __align__(16) __half g_tWahh[256 * 768];
__device__ __align__(16) __half g_tWq[256 * 256];
__device__ __align__(16) __half g_tWproj[512 * 256];
__device__ __align__(16) __half g_tWd1i[256 * 768];
__device__ __align__(16) __half g_tWd1h[256 * 768];
__device__ __align__(16) __half g_tWd2i[256 * 768];
__device__ __align__(16) __half g_tWd2h[256 * 768];
__device__ __align__(16) __half g_tWmel[256 * 512];   // O padded 400->512

// ------------------------- helpers -------------------------
__device__ __forceinline__ float tanh_approx(float x) {
    float y;
    asm("tanh.approx.f32 %0, %1;" : "=f"(y) : "f"(x));
    return y;
}
__device__ __forceinline__ float sigmoidf_(float x) {
    return 1.0f / (1.0f + __expf(-x));
}
__device__ __forceinline__ unsigned long long f2pack(float x, float y) {
    unsigned long long d;
    asm("mov.b64 %0, {%1, %2};" : "=l"(d) : "f"(x), "f"(y));
    return d;
}
__device__ __forceinline__ float2 f2unpack(unsigned long long v) {
    float2 r;
    asm("mov.b64 {%0, %1}, %2;" : "=f"(r.x), "=f"(r.y) : "l"(v));
    return r;
}
__device__ __forceinline__ unsigned long long ffma2(unsigned long long a,
                                                    unsigned long long b,
                                                    unsigned long long c) {
    unsigned long long d;
    asm("fma.rn.f32x2 %0, %1, %2, %3;" : "=l"(d) : "l"(a), "l"(b), "l"(c));
    return d;
}

// ------------------------- prep kernel: pm + transpose-convert ---------------
struct PrepArgs {
    const float* src[11];
    __half* dst[11];
    int O[11], K[11], OP[11];
    int start[12];
    const float* enc;
    const float* memW;
    float* pm;
};

__global__ void __launch_bounds__(PREP_TB) prep_kernel(PrepArgs a) {
    int bid = blockIdx.x;
    if (bid < PM_BLOCKS) {
        __shared__ __align__(16) float se[PM_ROWS][DMODEL];
        size_t row0 = (size_t)bid * PM_ROWS;
        for (int i = threadIdx.x; i < PM_ROWS * DMODEL; i += PREP_TB)
            se[i >> 8][i & 255] = a.enc[row0 * DMODEL + i];
        __syncthreads();
        int o = threadIdx.x;
        float acc[PM_ROWS];
#pragma unroll
        for (int r = 0; r < PM_ROWS; ++r) acc[r] = 0.f;
        const float4* W4 = reinterpret_cast<const float4*>(a.memW + (size_t)o * DMODEL);
#pragma unroll 4
        for (int k4 = 0; k4 < DMODEL / 4; ++k4) {
            float4 w = __ldg(&W4[k4]);
#pragma unroll
            for (int r = 0; r < PM_ROWS; ++r) {
                const float* e = &se[r][k4 * 4];
                float s = acc[r];
                s = fmaf(w.x, e[0], s); s = fmaf(w.y, e[1], s);
                s = fmaf(w.z, e[2], s); s = fmaf(w.w, e[3], s);
                acc[r] = s;
            }
        }
#pragma unroll
        for (int r = 0; r < PM_ROWS; ++r)
            a.pm[(row0 + r) * DMODEL + o] = acc[r];
        return;
    }
    int tb = bid - PM_BLOCKS;
    int m = 0;
#pragma unroll
    for (int j = 0; j < 11; ++j)
        if (tb >= a.start[j + 1]) m = j + 1;
    int local = (tb - a.start[m]) * PREP_TB + threadIdx.x;
    int OP = a.OP[m], O = a.O[m], K = a.K[m];
    int k = local / OP, o = local - k * OP;
    __half v = (o < O) ? __float2half_rn(a.src[m][(size_t)o * K + k]) : __half(0.f);
    a.dst[m][local] = v;
}

// ------------------------- gemv task (one warp, 128 outputs, k-chunk) --------
// WT [K][Ostride] fp16; x4[k] = float4 of 4 batch rows; pp -> partial [4][128]
__device__ __forceinline__ void gemv_task(const __half* __restrict__ WT, int Ostride,
                                          const float4* __restrict__ x4,
                                          int o0, int k0, int k1,
                                          float* __restrict__ pp) {
    const int lane = threadIdx.x & 31;
    const __half* base = WT + (size_t)k0 * Ostride + o0 + lane * 4;
    unsigned long long a01[4], a23[4];
#pragma unroll
    for (int j = 0; j < 4; ++j) { a01[j] = 0ull; a23[j] = 0ull; }
#pragma unroll 4
    for (int k = k0; k < k1; ++k) {
        uint2 wv = __ldg(reinterpret_cast<const uint2*>(base));
        base += Ostride;
        float2 w01 = __half22float2(*reinterpret_cast<__half2*>(&wv.x));
        float2 w23 = __half22float2(*reinterpret_cast<__half2*>(&wv.y));
        float4 xv = x4[k];
        unsigned long long x01 = f2pack(xv.x, xv.y);
        unsigned long long x23 = f2pack(xv.z, xv.w);
        unsigned long long wa = f2pack(w01.x, w01.x);
        unsigned long long wb = f2pack(w01.y, w01.y);
        unsigned long long wc = f2pack(w23.x, w23.x);
        unsigned long long wd = f2pack(w23.y, w23.y);
        a01[0] = ffma2(wa, x01, a01[0]); a23[0] = ffma2(wa, x23, a23[0]);
        a01[1] = ffma2(wb, x01, a01[1]); a23[1] = ffma2(wb, x23, a23[1]);
        a01[2] = ffma2(wc, x01, a01[2]); a23[2] = ffma2(wc, x23, a23[2]);
        a01[3] = ffma2(wd, x01, a01[3]); a23[3] = ffma2(wd, x23, a23[3]);
    }
    float4 r0, r1, r2, r3;
    float2 t;
    t = f2unpack(a01[0]); r0.x = t.x; r1.x = t.y;
    t = f2unpack(a23[0]); r2.x = t.x; r3.x = t.y;
    t = f2unpack(a01[1]); r0.y = t.x; r1.y = t.y;
    t = f2unpack(a23[1]); r2.y = t.x; r3.y = t.y;
    t = f2unpack(a01[2]); r0.z = t.x; r1.z = t.y;
    t = f2unpack(a23[2]); r2.z = t.x; r3.z = t.y;
    t = f2unpack(a01[3]); r0.w = t.x; r1.w = t.y;
    t = f2unpack(a23[3]); r2.w = t.x; r3.w = t.y;
    reinterpret_cast<float4*>(pp + 0 * 128)[lane] = r0;
    reinterpret_cast<float4*>(pp + 1 * 128)[lane] = r1;
    reinterpret_cast<float4*>(pp + 2 * 128)[lane] = r2;
    reinterpret_cast<float4*>(pp + 3 * 128)[lane] = r3;
}

// sum partials: tasks ordered (o>>7)*KC + c starting at task index tb
__device__ __forceinline__ float red(const float* __restrict__ part, int tb, int KC,
                                     int g, int row) {
    const float* p = part + (size_t)(tb + (g >> 7) * KC) * 512 + row * 128 + (g & 127);
    float s = 0.f;
#pragma unroll 8
    for (int c = 0; c < KC; ++c) s += p[c * 512];
    return s;
}

// ------------------------- shared memory layout ----------------------------
struct __align__(16) SD {
    float part[30720];        // 122880 B (max: attn GRU 60 tasks); also ctx scratch
    float4 in4[400];
    float4 p14[256];
    float4 x4[384];           // [0:128)=prenet2 out, [128:384)=ctx
    float4 cat4[512];
    float4 d4[256];
    float4 ah4[256];
    float4 h14[256];
    float4 h24[256];
    float qT[4][256];
    float sc[4][TENC];
    float v[256];
    int len_s[4];
    float b_p1[256]; float b_p2[128];
    float b_aih[768]; float b_ahh[768];
    float b_proj[256];
    float b_d1i[768]; float b_d1h[768];
    float b_d2i[768]; float b_d2h[768];
    float b_mel[400];
};

// ------------------------- main persistent decoder -------------------------
__global__ void __launch_bounds__(TB, 1) decoder_kernel(
    const float* __restrict__ enc, const float* __restrict__ inputs,
    const int* __restrict__ memlen,
    const float* __restrict__ gb_p1, const float* __restrict__ gb_p2,
    const float* __restrict__ gb_aih, const float* __restrict__ gb_ahh,
    const float* __restrict__ vW,
    const float* __restrict__ gb_proj,
    const float* __restrict__ gb_d1i, const float* __restrict__ gb_d1h,
    const float* __restrict__ gb_d2i, const float* __restrict__ gb_d2h,
    const float* __restrict__ gb_mel,
    float* __restrict__ out, int write_align) {
    extern __shared__ unsigned char smem_raw[];
    SD* s = reinterpret_cast<SD*>(smem_raw);

    const int tid = threadIdx.x;
    const int wid = tid >> 5;
    const int lane = tid & 31;
    const int b0 = blockIdx.x * ROWS;
    const int oo = tid & 255;      // output index for reduces
    const int orow = tid >> 8;     // row index for reduces (0..3)

    // init state + preload biases/v/lens
    {
        float4 z4 = make_float4(0.f, 0.f, 0.f, 0.f);
        if (tid < 256) {
            s->ah4[tid] = z4; s->h14[tid] = z4; s->h24[tid] = z4;
            s->x4[128 + tid] = z4;
            s->v[tid] = vW[tid];
            s->b_p1[tid] = gb_p1[tid];
            s->b_proj[tid] = gb_proj[tid];
        }
        if (tid >= 256 && tid < 384) s->b_p2[tid - 256] = gb_p2[tid - 256];
        if (tid < 768) {
            s->b_aih[tid] = gb_aih[tid]; s->b_ahh[tid] = gb_ahh[tid];
            s->b_d1i[tid] = gb_d1i[tid]; s->b_d1h[tid] = gb_d1h[tid];
            s->b_d2i[tid] = gb_d2i[tid]; s->b_d2h[tid] = gb_d2h[tid];
        }
        if (tid >= 512 && tid < 912) s->b_mel[tid - 512] = gb_mel[tid - 512];
        if (tid < 4) s->len_s[tid] = memlen[b0 + tid];
    }
    __syncthreads();

    float* outMel = out;
    float* outAl = out + (size_t)BATCH * TD * INR;

    for (int t = 0; t < TD; ++t) {
        // ---- teacher-forced input: in4[o].row ----
        if (t == 0) {
            for (int i = tid; i < INR; i += TB)
                s->in4[i] = make_float4(0.f, 0.f, 0.f, 0.f);
        } else {
            for (int idx = tid; idx < 4 * INR; idx += TB) {
                int row = idx / INR, o = idx - row * INR;
                float vv = inputs[((size_t)(b0 + row) * 1000 + (size_t)(t - 1) * 5) * 80 + o];
                reinterpret_cast<float*>(&s->in4[o])[row] = vv;
            }
        }
        __syncthreads();

        // ---- A: prenet1 (O=256,K=400): 32 tasks, CH=25 ----
        for (int task = wid; task < 32; task += 32) {
            int ot = task >> 4, c = task & 15;
            gemv_task(g_tWp1, 256, s->in4, ot * 128, c * 25, c * 25 + 25,
                      s->part + (size_t)task * 512);
        }
        __syncthreads();
        {
            float r = red(s->part, 0, 16, oo, orow) + s->b_p1[oo];
            reinterpret_cast<float*>(&s->p14[oo])[orow] = fmaxf(r, 0.f);
        }
        __syncthreads();

        // ---- B: prenet2 (O=128,K=256): 16 tasks, CH=16 ----
        for (int task = wid; task < 16; task += 32)
            gemv_task(g_tWp2, 128, s->p14, 0, task * 16, task * 16 + 16,
                      s->part + (size_t)task * 512);
        __syncthreads();
        if (oo < 128) {
            float r = red(s->part, 0, 16, oo, orow) + s->b_p2[oo];
            reinterpret_cast<float*>(&s->x4[oo])[orow] = fmaxf(r, 0.f);
        }
        __syncthreads();

        // ---- C: attention GRU gates: gi 36 tasks (CH=64) + gh 24 tasks (CH=64) ----
        for (int task = wid; task < 60; task += 32) {
            if (task < 36) {
                int ot = task / 6, c = task - ot * 6;
                gemv_task(g_tWaih, 768, s->x4, ot * 128, c * 64, c * 64 + 64,
                          s->part + (size_t)task * 512);
            } else {
                int t2 = task - 36;
                int ot = t2 >> 2, c = t2 & 3;
                gemv_task(g_tWahh, 768, s->ah4, ot * 128, c * 64, c * 64 + 64,
                          s->part + (size_t)task * 512);
            }
        }
        __syncthreads();
        {
            float ir = red(s->part, 0, 6, oo, orow) + s->b_aih[oo];
            float iz = red(s->part, 0, 6, 256 + oo, orow) + s->b_aih[256 + oo];
            float in = red(s->part, 0, 6, 512 + oo, orow) + s->b_aih[512 + oo];
            float hr = red(s->part, 36, 4, oo, orow) + s->b_ahh[oo];
            float hz = red(s->part, 36, 4, 256 + oo, orow) + s->b_ahh[256 + oo];
            float hn = red(s->part, 36, 4, 512 + oo, orow) + s->b_ahh[512 + oo];
            float hp = reinterpret_cast<float*>(&s->ah4[oo])[orow];
            float rg = sigmoidf_(ir + hr);
            float z = sigmoidf_(iz + hz);
            float n = tanhf(in + rg * hn);
            float h = (1.f - z) * n + z * hp;
            reinterpret_cast<float*>(&s->ah4[oo])[orow] = h;
            reinterpret_cast<float*>(&s->cat4[oo])[orow] = h;
        }
        __syncthreads();

        // ---- D: query (O=256,K=256): 16 tasks, CH=32 ----
        for (int task = wid; task < 16; task += 32) {
            int ot = task >> 3, c = task & 7;
            gemv_task(g_tWq, 256, s->ah4, ot * 128, c * 32, c * 32 + 32,
                      s->part + (size_t)task * 512);
        }
        __syncthreads();
        s->qT[orow][oo] = red(s->part, 0, 8, oo, orow);
        __syncthreads();

        // ---- E: Bahdanau scores: warp per (row, tt) ----
        for (int task = wid; task < 4 * TENC; task += 32) {
            int row = task & 3, tt = task >> 2;
            const float4* P = reinterpret_cast<const float4*>(
                g_pm + ((size_t)(b0 + row) * TENC + tt) * DMODEL);
            const float4* Q = reinterpret_cast<const float4*>(s->qT[row]);
            const float4* V = reinterpret_cast<const float4*>(s->v);
            float acc = 0.f;
#pragma unroll
            for (int u = 0; u < 2; ++u) {
                int k4 = u * 32 + lane;
                float4 p = __ldg(&P[k4]);
                float4 q = Q[k4], v = V[k4];
                acc += v.x * tanh_approx(p.x + q.x);
                acc += v.y * tanh_approx(p.y + q.y);
                acc += v.z * tanh_approx(p.z + q.z);
                acc += v.w * tanh_approx(p.w + q.w);
            }
#pragma unroll
            for (int sh = 16; sh; sh >>= 1) acc += __shfl_xor_sync(0xffffffffu, acc, sh);
            if (lane == 0)
                s->sc[row][tt] = (tt < s->len_s[row]) ? acc : -1e9f;
        }
        __syncthreads();

        // ---- F: softmax per row (warps 0..3) + alignment output ----
        if (wid < 4) {
            int row = wid;
            float m = -1e30f;
            for (int i = lane; i < TENC; i += 32) m = fmaxf(m, s->sc[row][i]);
#pragma unroll
            for (int sh = 16; sh; sh >>= 1) m = fmaxf(m, __shfl_xor_sync(0xffffffffu, m, sh));
            float sum = 0.f;
            for (int i = lane; i < TENC; i += 32) {
                float e = __expf(s->sc[row][i] - m);
                s->sc[row][i] = e;
                sum += e;
            }
#pragma unroll
            for (int sh = 16; sh; sh >>= 1) sum += __shfl_xor_sync(0xffffffffu, sum, sh);
            float inv = 1.f / sum;
            float* ao = outAl + ((size_t)(b0 + row) * TD + t) * TENC;
            for (int i = lane; i < TENC; i += 32) {
                float a = s->sc[row][i] * inv;
                s->sc[row][i] = a;
                if (write_align) ao[i] = a;
            }
        }
        __syncthreads();

        // ---- G: attention context (64 o-groups x 4 rows x 4 t-splits) ----
        {
            int g = tid & 63, row = (tid >> 6) & 3, th = tid >> 8;
            const float4* E = reinterpret_cast<const float4*>(
                                  enc + (size_t)(b0 + row) * TENC * DMODEL) + g;
            const float* scp = s->sc[row];
            float4 acc = make_float4(0.f, 0.f, 0.f, 0.f);
            int tt0 = th * 50;
#pragma unroll 5
            for (int tt = tt0; tt < tt0 + 50; ++tt) {
                float a = scp[tt];
                float4 e = __ldg(&E[(size_t)tt * 64]);
                acc.x = fmaf(a, e.x, acc.x);
                acc.y = fmaf(a, e.y, acc.y);
                acc.z = fmaf(a, e.z, acc.z);
                acc.w = fmaf(a, e.w, acc.w);
            }
            reinterpret_cast<float4*>(s->part)[(th * 4 + row) * 64 + g] = acc;
        }
        __syncthreads();
        if (tid < 256) {
            int g = tid & 63, row = tid >> 6;
            const float4* scr = reinterpret_cast<const float4*>(s->part);
            float4 c = scr[(0 * 4 + row) * 64 + g];
            float4 c1 = scr[(1 * 4 + row) * 64 + g];
            float4 c2 = scr[(2 * 4 + row) * 64 + g];
            float4 c3 = scr[(3 * 4 + row) * 64 + g];
            c.x += c1.x + c2.x + c3.x;
            c.y += c1.y + c2.y + c3.y;
            c.z += c1.z + c2.z + c3.z;
            c.w += c1.w + c2.w + c3.w;
            int o = g * 4;
            reinterpret_cast<float*>(&s->x4[128 + o])[row] = c.x;
            reinterpret_cast<float*>(&s->x4[128 + o + 1])[row] = c.y;
            reinterpret_cast<float*>(&s->x4[128 + o + 2])[row] = c.z;
            reinterpret_cast<float*>(&s->x4[128 + o + 3])[row] = c.w;
            reinterpret_cast<float*>(&s->cat4[256 + o])[row] = c.x;
            reinterpret_cast<float*>(&s->cat4[256 + o + 1])[row] = c.y;
            reinterpret_cast<float*>(&s->cat4[256 + o + 2])[row] = c.z;
            reinterpret_cast<float*>(&s->cat4[256 + o + 3])[row] = c.w;
        }
        __syncthreads();

        // ---- H: proj (O=256,K=512): 16 tasks, CH=64 ----
        for (int task = wid; task < 16; task += 32) {
            int ot = task >> 3, c = task & 7;
            gemv_task(g_tWproj, 256, s->cat4, ot * 128, c * 64, c * 64 + 64,
                      s->part + (size_t)task * 512);
        }
        __syncthreads();
        {
            float r = red(s->part, 0, 8, oo, orow) + s->b_proj[oo];
            reinterpret_cast<float*>(&s->d4[oo])[orow] = r;
        }
        __syncthreads();

        // ---- I: decoder GRU 1: 24 + 24 tasks, CH=64 ----
        for (int task = wid; task < 48; task += 32) {
            if (task < 24) {
                int ot = task >> 2, c = task & 3;
                gemv_task(g_tWd1i, 768, s->d4, ot * 128, c * 64, c * 64 + 64,
                          s->part + (size_t)task * 512);
            } else {
                int t2 = task - 24;
                int ot = t2 >> 2, c = t2 & 3;
                gemv_task(g_tWd1h, 768, s->h14, ot * 128, c * 64, c * 64 + 64,
                          s->part + (size_t)task * 512);
            }
        }
        __syncthreads();
        {
            float ir = red(s->part, 0, 4, oo, orow) + s->b_d1i[oo];
            float iz = red(s->part, 0, 4, 256 + oo, orow) + s->b_d1i[256 + oo];
            float in = red(s->part, 0, 4, 512 + oo, orow) + s->b_d1i[512 + oo];
            float hr = red(s->part, 24, 4, oo, orow) + s->b_d1h[oo];
            float hz = red(s->part, 24, 4, 256 + oo, orow) + s->b_d1h[256 + oo];
            float hn = red(s->part, 24, 4, 512 + oo, orow) + s->b_d1h[512 + oo];
            float hp = reinterpret_cast<float*>(&s->h14[oo])[orow];
            float rg = sigmoidf_(ir + hr);
            float z = sigmoidf_(iz + hz);
            float n = tanhf(in + rg * hn);
            float h = (1.f - z) * n + z * hp;
            reinterpret_cast<float*>(&s->h14[oo])[orow] = h;
            reinterpret_cast<float*>(&s->d4[oo])[orow] += h;
        }
        __syncthreads();

        // ---- J: decoder GRU 2: 24 + 24 tasks, CH=64 ----
        for (int task = wid; task < 48; task += 32) {
            if (task < 24) {
                int ot = task >> 2, c = task & 3;
                gemv_task(g_tWd2i, 768, s->d4, ot * 128, c * 64, c * 64 + 64,
                          s->part + (size_t)task * 512);
            } else {
                int t2 = task - 24;
                int ot = t2 >> 2, c = t2 & 3;
                gemv_task(g_tWd2h, 768, s->h24, ot * 128, c * 64, c * 64 + 64,
                          s->part + (size_t)task * 512);
            }
        }
        __syncthreads();
        {
            float ir = red(s->part, 0, 4, oo, orow) + s->b_d2i[oo];
            float iz = red(s->part, 0, 4, 256 + oo, orow) + s->b_d2i[256 + oo];
            float in = red(s->part, 0, 4, 512 + oo, orow) + s->b_d2i[512 + oo];
            float hr = red(s->part, 24, 4, oo, orow) + s->b_d2h[oo];
            float hz = red(s->part, 24, 4, 256 + oo, orow) + s->b_d2h[256 + oo];
            float hn = red(s->part, 24, 4, 512 + oo, orow) + s->b_d2h[512 + oo];
            float hp = reinterpret_cast<float*>(&s->h24[oo])[orow];
            float rg = sigmoidf_(ir + hr);
            float z = sigmoidf_(iz + hz);
            float n = tanhf(in + rg * hn);
            float h = (1.f - z) * n + z * hp;
            reinterpret_cast<float*>(&s->h24[oo])[orow] = h;
            reinterpret_cast<float*>(&s->d4[oo])[orow] += h;
        }
        __syncthreads();

        // ---- K: mel (O=512 pad, K=256): 32 tasks, CH=32 ----
        for (int task = wid; task < 32; task += 32) {
            int ot = task >> 3, c = task & 7;
            gemv_task(g_tWmel, 512, s->d4, ot * 128, c * 32, c * 32 + 32,
                      s->part + (size_t)task * 512);
        }
        __syncthreads();
        for (int idx = tid; idx < 4 * INR; idx += TB) {
            int row = idx / INR, o = idx - row * INR;
            float r = red(s->part, 0, 8, o, row) + s->b_mel[o];
            outMel[((size_t)(b0 + row) * TD + t) * INR + o] = r;
        }
        __syncthreads();
    }
}

// ------------------------- launch -------------------------
extern "C" void kernel_launch(void* const* d_in, const int* in_sizes, int n_in,
                              void* d_out, int out_size) {
    const float* enc = (const float*)d_in[0];
    const float* inputs = (const float*)d_in[1];
    const int* memlen = (const int*)d_in[2];

    PrepArgs a;
    static const int srcIdx[11] = {3, 5, 7, 9, 12, 14, 16, 18, 20, 22, 24};
    static const int Oarr[11] = {256, 128, 768, 768, 256, 256, 768, 768, 768, 768, 400};
    static const int Karr[11] = {400, 256, 384, 256, 256, 512, 256, 256, 256, 256, 256};
    static const int OParr[11] = {256, 128, 768, 768, 256, 256, 768, 768, 768, 768, 512};

    void* dsts[11];
    cudaGetSymbolAddress(&dsts[0], g_tWp1);
    cudaGetSymbolAddress(&dsts[1], g_tWp2);
    cudaGetSymbolAddress(&dsts[2], g_tWaih);
    cudaGetSymbolAddress(&dsts[3], g_tWahh);
    cudaGetSymbolAddress(&dsts[4], g_tWq);
    cudaGetSymbolAddress(&dsts[5], g_tWproj);
    cudaGetSymbolAddress(&dsts[6], g_tWd1i);
    cudaGetSymbolAddress(&dsts[7], g_tWd1h);
    cudaGetSymbolAddress(&dsts[8], g_tWd2i);
    cudaGetSymbolAddress(&dsts[9], g_tWd2h);
    cudaGetSymbolAddress(&dsts[10], g_tWmel);

    int cum = 0;
    for (int m = 0; m < 11; ++m) {
        a.src[m] = (const float*)d_in[srcIdx[m]];
        a.dst[m] = (__half*)dsts[m];
        a.O[m] = Oarr[m]; a.K[m] = Karr[m]; a.OP[m] = OParr[m];
        a.start[m] = cum;
        cum += (Karr[m] * OParr[m]) / PREP_TB;
    }
    a.start[11] = cum;
    a.enc = enc;
    a.memW = (const float*)d_in[11];
    cudaGetSymbolAddress((void**)&a.pm, g_pm);

    prep_kernel<<<PM_BLOCKS + cum, PREP_TB>>>(a);

    static bool attr_done = false;
    if (!attr_done) {
        cudaFuncSetAttribute(decoder_kernel,
                             cudaFuncAttributeMaxDynamicSharedMemorySize,
                             (int)sizeof(SD));
        attr_done = true;
    }

    int write_align = (out_size >= BATCH * TD * (INR + TENC)) ? 1 : 0;

    decoder_kernel<<<NGROUPS, TB, sizeof(SD)>>>(
        enc, inputs, memlen,
        (const float*)d_in[4], (const float*)d_in[6],
        (const float*)d_in[8], (const float*)d_in[10],
        (const float*)d_in[13],
        (const float*)d_in[15],
        (const float*)d_in[17], (const float*)d_in[19],
        (const float*)d_in[21], (const float*)d_in[23],
        (const float*)d_in[25],
        (float*)d_out, write_align);
}

// round 8
// speedup vs baseline: 4.0860x; 1.7001x over previous
#include <cuda_runtime.h>
#include <cuda_fp16.h>
#include <cstdint>
#include <cstddef>

#define TB 1024
#define PREP_TB 256
#define BATCH 256
#define ROWS 2
#define NGROUPS (BATCH / ROWS)       // 128 CTAs
#define TENC 200
#define TD 200
#define DMODEL 256
#define INR 400
#define PM_ROWS 16
#define PM_BLOCKS (BATCH * TENC / PM_ROWS)          // 3200
#define ENC_ELEMS (BATCH * TENC * DMODEL)           // 13107200
#define ENC_CVT_BLOCKS (ENC_ELEMS / (PREP_TB * 8))  // 6400

// ------------------------- persistent device scratch -------------------------
__device__ __align__(16) __half g_pmh[ENC_ELEMS];   // processed_memory fp16
__device__ __align__(16) __half g_ench[ENC_ELEMS];  // encoder outputs fp16

// fp16 weights, TRANSPOSED [K][O_pad]
__device__ __align__(16) __half g_tWp1[400 * 256];
__device__ __align__(16) __half g_tWp2[256 * 128];
__device__ __align__(16) __half g_tWaih[384 * 768];
__device__ __align__(16) __half g_tWahh[256 * 768];
__device__ __align__(16) __half g_tWq[256 * 256];
__device__ __align__(16) __half g_tWproj[512 * 256];
__device__ __align__(16) __half g_tWd1i[256 * 768];
__device__ __align__(16) __half g_tWd1h[256 * 768];
__device__ __align__(16) __half g_tWd2i[256 * 768];
__device__ __align__(16) __half g_tWd2h[256 * 768];
__device__ __align__(16) __half g_tWmel[256 * 512];   // O padded 400->512

// ------------------------- helpers -------------------------
__device__ __forceinline__ float tanh_approx(float x) {
    float y;
    asm("tanh.approx.f32 %0, %1;" : "=f"(y) : "f"(x));
    return y;
}
__device__ __forceinline__ float sigmoidf_(float x) {
    return 1.0f / (1.0f + __expf(-x));
}
__device__ __forceinline__ unsigned long long f2pack(float x, float y) {
    unsigned long long d;
    asm("mov.b64 %0, {%1, %2};" : "=l"(d) : "f"(x), "f"(y));
    return d;
}
__device__ __forceinline__ float2 f2unpack(unsigned long long v) {
    float2 r;
    asm("mov.b64 {%0, %1}, %2;" : "=f"(r.x), "=f"(r.y) : "l"(v));
    return r;
}
__device__ __forceinline__ unsigned long long ffma2(unsigned long long a,
                                                    unsigned long long b,
                                                    unsigned long long c) {
    unsigned long long d;
    asm("fma.rn.f32x2 %0, %1, %2, %3;" : "=l"(d) : "l"(a), "l"(b), "l"(c));
    return d;
}

// ------------------------- prep kernel ---------------------------------------
struct PrepArgs {
    const float* src[11];
    __half* dst[11];
    int O[11], K[11], OP[11];
    int start[12];
    const float* enc;
    const float* memW;
    __half* pm;
    __half* ench;
};

__global__ void __launch_bounds__(PREP_TB) prep_kernel(PrepArgs a) {
    int bid = blockIdx.x;
    if (bid < PM_BLOCKS) {
        __shared__ __align__(16) float se[PM_ROWS][DMODEL];
        size_t row0 = (size_t)bid * PM_ROWS;
        for (int i = threadIdx.x; i < PM_ROWS * DMODEL; i += PREP_TB)
            se[i >> 8][i & 255] = a.enc[row0 * DMODEL + i];
        __syncthreads();
        int o = threadIdx.x;
        float acc[PM_ROWS];
#pragma unroll
        for (int r = 0; r < PM_ROWS; ++r) acc[r] = 0.f;
        const float4* W4 = reinterpret_cast<const float4*>(a.memW + (size_t)o * DMODEL);
#pragma unroll 4
        for (int k4 = 0; k4 < DMODEL / 4; ++k4) {
            float4 w = __ldg(&W4[k4]);
#pragma unroll
            for (int r = 0; r < PM_ROWS; ++r) {
                const float* e = &se[r][k4 * 4];
                float s = acc[r];
                s = fmaf(w.x, e[0], s); s = fmaf(w.y, e[1], s);
                s = fmaf(w.z, e[2], s); s = fmaf(w.w, e[3], s);
                acc[r] = s;
            }
        }
#pragma unroll
        for (int r = 0; r < PM_ROWS; ++r)
            a.pm[(row0 + r) * DMODEL + o] = __float2half_rn(acc[r]);
        return;
    }
    int tb = bid - PM_BLOCKS;
    if (tb < a.start[11]) {
        int m = 0;
#pragma unroll
        for (int j = 0; j < 11; ++j)
            if (tb >= a.start[j + 1]) m = j + 1;
        int local = (tb - a.start[m]) * PREP_TB + threadIdx.x;
        int OP = a.OP[m], O = a.O[m], K = a.K[m];
        int k = local / OP, o = local - k * OP;
        __half v = (o < O) ? __float2half_rn(a.src[m][(size_t)o * K + k]) : __half(0.f);
        a.dst[m][local] = v;
        return;
    }
    // enc fp32 -> fp16
    int e = tb - a.start[11];
    size_t i0 = ((size_t)e * PREP_TB + threadIdx.x) * 8;
    const float4* S4 = reinterpret_cast<const float4*>(a.enc + i0);
    float4 f0 = S4[0], f1 = S4[1];
    __half2 h0 = __floats2half2_rn(f0.x, f0.y);
    __half2 h1 = __floats2half2_rn(f0.z, f0.w);
    __half2 h2 = __floats2half2_rn(f1.x, f1.y);
    __half2 h3 = __floats2half2_rn(f1.z, f1.w);
    uint4 outv;
    outv.x = *reinterpret_cast<uint32_t*>(&h0);
    outv.y = *reinterpret_cast<uint32_t*>(&h1);
    outv.z = *reinterpret_cast<uint32_t*>(&h2);
    outv.w = *reinterpret_cast<uint32_t*>(&h3);
    *reinterpret_cast<uint4*>(a.ench + i0) = outv;
}

// ------------------------- gemv task (one warp, 128 outputs, 2 rows) ---------
// WT [K][Ostride] fp16; x2[k] = (row0,row1); pp -> partial [2][128]
__device__ __forceinline__ void gemv_task(const __half* __restrict__ WT, int Ostride,
                                          const float2* __restrict__ x2,
                                          int o0, int k0, int k1,
                                          float* __restrict__ pp) {
    const int lane = threadIdx.x & 31;
    const __half* base = WT + (size_t)k0 * Ostride + o0 + lane * 4;
    unsigned long long a0[2], a1[2];   // [pair] rows 0,1
    a0[0] = a0[1] = a1[0] = a1[1] = 0ull;
#pragma unroll 4
    for (int k = k0; k < k1; ++k) {
        uint2 wv = __ldg(reinterpret_cast<const uint2*>(base));
        base += Ostride;
        float2 w01 = __half22float2(*reinterpret_cast<__half2*>(&wv.x));
        float2 w23 = __half22float2(*reinterpret_cast<__half2*>(&wv.y));
        float2 xv = x2[k];
        unsigned long long xr0 = f2pack(xv.x, xv.x);
        unsigned long long xr1 = f2pack(xv.y, xv.y);
        unsigned long long wA = f2pack(w01.x, w01.y);
        unsigned long long wB = f2pack(w23.x, w23.y);
        a0[0] = ffma2(wA, xr0, a0[0]);
        a1[0] = ffma2(wA, xr1, a1[0]);
        a0[1] = ffma2(wB, xr0, a0[1]);
        a1[1] = ffma2(wB, xr1, a1[1]);
    }
    float2 p0 = f2unpack(a0[0]), p1 = f2unpack(a0[1]);
    float2 q0 = f2unpack(a1[0]), q1 = f2unpack(a1[1]);
    reinterpret_cast<float4*>(pp)[lane] = make_float4(p0.x, p0.y, p1.x, p1.y);
    reinterpret_cast<float4*>(pp + 128)[lane] = make_float4(q0.x, q0.y, q1.x, q1.y);
}

// partial layout per task: [2][128]; tasks (o>>7)*NC + c starting at tb
template <int NC>
__device__ __forceinline__ float redN(const float* __restrict__ part, int tb,
                                      int o, int row) {
    const float* p = part + (size_t)(tb + (o >> 7) * NC) * 256 + row * 128 + (o & 127);
    float s = 0.f;
#pragma unroll
    for (int c = 0; c < NC; ++c) s += p[c * 256];
    return s;
}

// ------------------------- shared memory layout ----------------------------
struct __align__(16) SD {
    float part[60 * 256];     // 61.4KB partials (also ctx scratch)
    float2 in2[400];
    float2 p12[256];
    float2 x2[384];           // [0:128)=prenet2, [128:384)=ctx
    float2 cat2[512];
    float2 d2[256];
    float2 ah2[256];
    float2 h12[256];
    float2 h22[256];
    float qT[2][256];
    float sc[2][TENC];
    float v[256];
    int len_s[2];
    float b_p1[256]; float b_p2[128];
    float b_aih[768]; float b_ahh[768];
    float b_proj[256];
    float b_d1i[768]; float b_d1h[768];
    float b_d2i[768]; float b_d2h[768];
    float b_mel[400];
};

// ------------------------- main persistent decoder -------------------------
__global__ void __launch_bounds__(TB, 1) decoder_kernel(
    const float* __restrict__ inputs,
    const int* __restrict__ memlen,
    const float* __restrict__ gb_p1, const float* __restrict__ gb_p2,
    const float* __restrict__ gb_aih, const float* __restrict__ gb_ahh,
    const float* __restrict__ vW,
    const float* __restrict__ gb_proj,
    const float* __restrict__ gb_d1i, const float* __restrict__ gb_d1h,
    const float* __restrict__ gb_d2i, const float* __restrict__ gb_d2h,
    const float* __restrict__ gb_mel,
    float* __restrict__ out, int write_align) {
    extern __shared__ unsigned char smem_raw[];
    SD* s = reinterpret_cast<SD*>(smem_raw);

    const int tid = threadIdx.x;
    const int wid = tid >> 5;
    const int lane = tid & 31;
    const int b0 = blockIdx.x * ROWS;

    // init state + biases
    {
        float2 z2 = make_float2(0.f, 0.f);
        if (tid < 256) {
            s->ah2[tid] = z2; s->h12[tid] = z2; s->h22[tid] = z2;
            s->x2[128 + tid] = z2;
            s->v[tid] = vW[tid];
            s->b_p1[tid] = gb_p1[tid];
            s->b_proj[tid] = gb_proj[tid];
        }
        if (tid >= 256 && tid < 384) s->b_p2[tid - 256] = gb_p2[tid - 256];
        if (tid < 768) {
            s->b_aih[tid] = gb_aih[tid]; s->b_ahh[tid] = gb_ahh[tid];
            s->b_d1i[tid] = gb_d1i[tid]; s->b_d1h[tid] = gb_d1h[tid];
            s->b_d2i[tid] = gb_d2i[tid]; s->b_d2h[tid] = gb_d2h[tid];
        }
        if (tid >= 512 && tid < 912) s->b_mel[tid - 512] = gb_mel[tid - 512];
        if (tid < 2) s->len_s[tid] = memlen[b0 + tid];
    }
    __syncthreads();

    float* outMel = out;
    float* outAl = out + (size_t)BATCH * TD * INR;

    for (int t = 0; t < TD; ++t) {
        // ---- teacher-forced input ----
        if (t == 0) {
            if (tid < 2 * INR) {
                int row = tid / INR, o = tid - row * INR;
                reinterpret_cast<float*>(&s->in2[o])[row] = 0.f;
            }
        } else {
            if (tid < 2 * INR) {
                int row = tid / INR, o = tid - row * INR;
                reinterpret_cast<float*>(&s->in2[o])[row] =
                    inputs[((size_t)(b0 + row) * 1000 + (size_t)(t - 1) * 5) * 80 + o];
            }
        }
        __syncthreads();

        // ---- A: prenet1 (O=256,K=400): 2 tiles x 16 chunks, CH=25 ----
        {
            int task = wid;
            int ot = task >> 4, c = task & 15;
            gemv_task(g_tWp1, 256, s->in2, ot * 128, c * 25, c * 25 + 25,
                      s->part + (size_t)task * 256);
        }
        __syncthreads();
        if (tid < 512) {
            int o = tid & 255, row = tid >> 8;
            float r = redN<16>(s->part, 0, o, row) + s->b_p1[o];
            reinterpret_cast<float*>(&s->p12[o])[row] = fmaxf(r, 0.f);
        }
        __syncthreads();

        // ---- B: prenet2 (O=128,K=256): 32 chunks, CH=8 ----
        {
            int task = wid;
            gemv_task(g_tWp2, 128, s->p12, 0, task * 8, task * 8 + 8,
                      s->part + (size_t)task * 256);
        }
        __syncthreads();
        if (tid < 256) {
            int o = tid & 127, row = tid >> 7;
            float r = redN<32>(s->part, 0, o, row) + s->b_p2[o];
            reinterpret_cast<float*>(&s->x2[o])[row] = fmaxf(r, 0.f);
        }
        __syncthreads();

        // ---- C: attention GRU: gi 36 tasks (CH=64) + gh 24 tasks (CH=64) ----
        for (int task = wid; task < 60; task += 32) {
            if (task < 36) {
                int ot = task / 6, c = task - ot * 6;
                gemv_task(g_tWaih, 768, s->x2, ot * 128, c * 64, c * 64 + 64,
                          s->part + (size_t)task * 256);
            } else {
                int t2 = task - 36;
                int ot = t2 >> 2, c = t2 & 3;
                gemv_task(g_tWahh, 768, s->ah2, ot * 128, c * 64, c * 64 + 64,
                          s->part + (size_t)task * 256);
            }
        }
        __syncthreads();
        if (tid < 512) {
            int o = tid & 255, row = tid >> 8;
            float ir = redN<6>(s->part, 0, o, row) + s->b_aih[o];
            float iz = redN<6>(s->part, 0, 256 + o, row) + s->b_aih[256 + o];
            float in = redN<6>(s->part, 0, 512 + o, row) + s->b_aih[512 + o];
            float hr = redN<4>(s->part, 36, o, row) + s->b_ahh[o];
            float hz = redN<4>(s->part, 36, 256 + o, row) + s->b_ahh[256 + o];
            float hn = redN<4>(s->part, 36, 512 + o, row) + s->b_ahh[512 + o];
            float hp = reinterpret_cast<float*>(&s->ah2[o])[row];
            float rg = sigmoidf_(ir + hr);
            float z = sigmoidf_(iz + hz);
            float n = tanhf(in + rg * hn);
            float h = (1.f - z) * n + z * hp;
            reinterpret_cast<float*>(&s->ah2[o])[row] = h;
            reinterpret_cast<float*>(&s->cat2[o])[row] = h;
        }
        __syncthreads();

        // ---- D: query (O=256,K=256): 2 tiles x 16 chunks, CH=16 ----
        {
            int task = wid;
            int ot = task >> 4, c = task & 15;
            gemv_task(g_tWq, 256, s->ah2, ot * 128, c * 16, c * 16 + 16,
                      s->part + (size_t)task * 256);
        }
        __syncthreads();
        if (tid < 512) {
            int o = tid & 255, row = tid >> 8;
            s->qT[row][o] = redN<16>(s->part, 0, o, row);
        }
        __syncthreads();

        // ---- E: Bahdanau scores (fp16 pm) ----
        for (int task = wid; task < 2 * TENC; task += 32) {
            int row = task & 1, tt = task >> 1;
            const uint4* P = reinterpret_cast<const uint4*>(
                g_pmh + ((size_t)(b0 + row) * TENC + tt) * DMODEL);
            uint4 pv = __ldg(&P[lane]);
            float2 p0 = __half22float2(*reinterpret_cast<__half2*>(&pv.x));
            float2 p1 = __half22float2(*reinterpret_cast<__half2*>(&pv.y));
            float2 p2 = __half22float2(*reinterpret_cast<__half2*>(&pv.z));
            float2 p3 = __half22float2(*reinterpret_cast<__half2*>(&pv.w));
            const float4* Q = reinterpret_cast<const float4*>(s->qT[row]);
            const float4* V = reinterpret_cast<const float4*>(s->v);
            float4 q0 = Q[lane * 2], q1 = Q[lane * 2 + 1];
            float4 v0 = V[lane * 2], v1 = V[lane * 2 + 1];
            float acc = 0.f;
            acc += v0.x * tanh_approx(p0.x + q0.x);
            acc += v0.y * tanh_approx(p0.y + q0.y);
            acc += v0.z * tanh_approx(p1.x + q0.z);
            acc += v0.w * tanh_approx(p1.y + q0.w);
            acc += v1.x * tanh_approx(p2.x + q1.x);
            acc += v1.y * tanh_approx(p2.y + q1.y);
            acc += v1.z * tanh_approx(p3.x + q1.z);
            acc += v1.w * tanh_approx(p3.y + q1.w);
#pragma unroll
            for (int sh = 16; sh; sh >>= 1) acc += __shfl_xor_sync(0xffffffffu, acc, sh);
            if (lane == 0)
                s->sc[row][tt] = (tt < s->len_s[row]) ? acc : -1e9f;
        }
        __syncthreads();

        // ---- F: softmax per row (warps 0..1) + alignment output ----
        if (wid < 2) {
            int row = wid;
            float m = -1e30f;
            for (int i = lane; i < TENC; i += 32) m = fmaxf(m, s->sc[row][i]);
#pragma unroll
            for (int sh = 16; sh; sh >>= 1) m = fmaxf(m, __shfl_xor_sync(0xffffffffu, m, sh));
            float sum = 0.f;
            for (int i = lane; i < TENC; i += 32) {
                float e = __expf(s->sc[row][i] - m);
                s->sc[row][i] = e;
                sum += e;
            }
#pragma unroll
            for (int sh = 16; sh; sh >>= 1) sum += __shfl_xor_sync(0xffffffffu, sum, sh);
            float inv = 1.f / sum;
            float* ao = outAl + ((size_t)(b0 + row) * TD + t) * TENC;
            for (int i = lane; i < TENC; i += 32) {
                float a = s->sc[row][i] * inv;
                s->sc[row][i] = a;
                if (write_align) ao[i] = a;
            }
        }
        __syncthreads();

        // ---- G: attention context (fp16 enc): g(64) x row(2) x ts(8x25) ----
        {
            int g = tid & 63, row = (tid >> 6) & 1, ts = tid >> 7;
            const uint2* E = reinterpret_cast<const uint2*>(
                                 g_ench + (size_t)(b0 + row) * TENC * DMODEL);
            const float* scp = s->sc[row];
            float4 acc = make_float4(0.f, 0.f, 0.f, 0.f);
            int tt0 = ts * 25;
#pragma unroll 5
            for (int tt = tt0; tt < tt0 + 25; ++tt) {
                float a = scp[tt];
                uint2 ev = __ldg(&E[tt * 64 + g]);
                float2 e0 = __half22float2(*reinterpret_cast<__half2*>(&ev.x));
                float2 e1 = __half22float2(*reinterpret_cast<__half2*>(&ev.y));
                acc.x = fmaf(a, e0.x, acc.x);
                acc.y = fmaf(a, e0.y, acc.y);
                acc.z = fmaf(a, e1.x, acc.z);
                acc.w = fmaf(a, e1.y, acc.w);
            }
            reinterpret_cast<float4*>(s->part)[(ts * 2 + row) * 64 + g] = acc;
        }
        __syncthreads();
        if (tid < 512) {
            int o = tid & 255, row = tid >> 8;
            int gg = o >> 2, comp = o & 3;
            const float* pf = s->part;
            float sv = 0.f;
#pragma unroll
            for (int ts = 0; ts < 8; ++ts)
                sv += pf[((ts * 2 + row) * 64 + gg) * 4 + comp];
            reinterpret_cast<float*>(&s->x2[128 + o])[row] = sv;
            reinterpret_cast<float*>(&s->cat2[256 + o])[row] = sv;
        }
        __syncthreads();

        // ---- H: proj (O=256,K=512): 2 tiles x 16 chunks, CH=32 ----
        {
            int task = wid;
            int ot = task >> 4, c = task & 15;
            gemv_task(g_tWproj, 256, s->cat2, ot * 128, c * 32, c * 32 + 32,
                      s->part + (size_t)task * 256);
        }
        __syncthreads();
        if (tid < 512) {
            int o = tid & 255, row = tid >> 8;
            float r = redN<16>(s->part, 0, o, row) + s->b_proj[o];
            reinterpret_cast<float*>(&s->d2[o])[row] = r;
        }
        __syncthreads();

        // ---- I/J: decoder GRUs: gi 24 + gh 24 tasks, CH=64 ----
#pragma unroll
        for (int gru = 0; gru < 2; ++gru) {
            const __half* Wi = gru ? g_tWd2i : g_tWd1i;
            const __half* Wh = gru ? g_tWd2h : g_tWd1h;
            const float* bi = gru ? s->b_d2i : s->b_d1i;
            const float* bh = gru ? s->b_d2h : s->b_d1h;
            float2* hstate = gru ? s->h22 : s->h12;
            for (int task = wid; task < 48; task += 32) {
                if (task < 24) {
                    int ot = task >> 2, c = task & 3;
                    gemv_task(Wi, 768, s->d2, ot * 128, c * 64, c * 64 + 64,
                              s->part + (size_t)task * 256);
                } else {
                    int t2 = task - 24;
                    int ot = t2 >> 2, c = t2 & 3;
                    gemv_task(Wh, 768, hstate, ot * 128, c * 64, c * 64 + 64,
                              s->part + (size_t)task * 256);
                }
            }
            __syncthreads();
            if (tid < 512) {
                int o = tid & 255, row = tid >> 8;
                float ir = redN<4>(s->part, 0, o, row) + bi[o];
                float iz = redN<4>(s->part, 0, 256 + o, row) + bi[256 + o];
                float in = redN<4>(s->part, 0, 512 + o, row) + bi[512 + o];
                float hr = redN<4>(s->part, 24, o, row) + bh[o];
                float hz = redN<4>(s->part, 24, 256 + o, row) + bh[256 + o];
                float hn = redN<4>(s->part, 24, 512 + o, row) + bh[512 + o];
                float hp = reinterpret_cast<float*>(&hstate[o])[row];
                float rg = sigmoidf_(ir + hr);
                float z = sigmoidf_(iz + hz);
                float n = tanhf(in + rg * hn);
                float h = (1.f - z) * n + z * hp;
                reinterpret_cast<float*>(&hstate[o])[row] = h;
                reinterpret_cast<float*>(&s->d2[o])[row] += h;
            }
            __syncthreads();
        }

        // ---- K: mel (O=512 pad, K=256): 4 tiles x 8 chunks, CH=32 ----
        {
            int task = wid;
            int ot = task >> 3, c = task & 7;
            gemv_task(g_tWmel, 512, s->d2, ot * 128, c * 32, c * 32 + 32,
                      s->part + (size_t)task * 256);
        }
        __syncthreads();
        if (tid < 2 * INR) {
            int row = tid / INR, o = tid - row * INR;
            float r = redN<8>(s->part, 0, o, row) + s->b_mel[o];
            outMel[((size_t)(b0 + row) * TD + t) * INR + o] = r;
        }
        __syncthreads();
    }
}

// ------------------------- launch -------------------------
extern "C" void kernel_launch(void* const* d_in, const int* in_sizes, int n_in,
                              void* d_out, int out_size) {
    const float* enc = (const float*)d_in[0];
    const float* inputs = (const float*)d_in[1];
    const int* memlen = (const int*)d_in[2];

    PrepArgs a;
    static const int srcIdx[11] = {3, 5, 7, 9, 12, 14, 16, 18, 20, 22, 24};
    static const int Oarr[11] = {256, 128, 768, 768, 256, 256, 768, 768, 768, 768, 400};
    static const int Karr[11] = {400, 256, 384, 256, 256, 512, 256, 256, 256, 256, 256};
    static const int OParr[11] = {256, 128, 768, 768, 256, 256, 768, 768, 768, 768, 512};

    void* dsts[11];
    cudaGetSymbolAddress(&dsts[0], g_tWp1);
    cudaGetSymbolAddress(&dsts[1], g_tWp2);
    cudaGetSymbolAddress(&dsts[2], g_tWaih);
    cudaGetSymbolAddress(&dsts[3], g_tWahh);
    cudaGetSymbolAddress(&dsts[4], g_tWq);
    cudaGetSymbolAddress(&dsts[5], g_tWproj);
    cudaGetSymbolAddress(&dsts[6], g_tWd1i);
    cudaGetSymbolAddress(&dsts[7], g_tWd1h);
    cudaGetSymbolAddress(&dsts[8], g_tWd2i);
    cudaGetSymbolAddress(&dsts[9], g_tWd2h);
    cudaGetSymbolAddress(&dsts[10], g_tWmel);

    int cum = 0;
    for (int m = 0; m < 11; ++m) {
        a.src[m] = (const float*)d_in[srcIdx[m]];
        a.dst[m] = (__half*)dsts[m];
        a.O[m] = Oarr[m]; a.K[m] = Karr[m]; a.OP[m] = OParr[m];
        a.start[m] = cum;
        cum += (Karr[m] * OParr[m]) / PREP_TB;
    }
    a.start[11] = cum;   // 6800
    a.enc = enc;
    a.memW = (const float*)d_in[11];
    cudaGetSymbolAddress((void**)&a.pm, g_pmh);
    cudaGetSymbolAddress((void**)&a.ench, g_ench);

    prep_kernel<<<PM_BLOCKS + cum + ENC_CVT_BLOCKS, PREP_TB>>>(a);

    static bool attr_done = false;
    if (!attr_done) {
        cudaFuncSetAttribute(decoder_kernel,
                             cudaFuncAttributeMaxDynamicSharedMemorySize,
                             (int)sizeof(SD));
        attr_done = true;
    }

    int write_align = (out_size >= BATCH * TD * (INR + TENC)) ? 1 : 0;

    decoder_kernel<<<NGROUPS, TB, sizeof(SD)>>>(
        inputs, memlen,
        (const float*)d_in[4], (const float*)d_in[6],
        (const float*)d_in[8], (const float*)d_in[10],
        (const float*)d_in[13],
        (const float*)d_in[15],
        (const float*)d_in[17], (const float*)d_in[19],
        (const float*)d_in[21], (const float*)d_in[23],
        (const float*)d_in[25],
        (float*)d_out, write_align);
}

// round 9
// speedup vs baseline: 4.8943x; 1.1978x over previous
#include <cuda_runtime.h>
#include <cuda_fp16.h>
#include <cstdint>
#include <cstddef>

#define TB 1024
#define PREP_TB 256
#define BATCH 256
#define ROWS 2
#define NGROUPS (BATCH / ROWS)       // 128 CTAs
#define TENC 200
#define TD 200
#define DMODEL 256
#define INR 400
#define PM_ROWS 16
#define PM_BLOCKS (BATCH * TENC / PM_ROWS)          // 3200
#define ENC_ELEMS (BATCH * TENC * DMODEL)           // 13107200
#define ENC_CVT_BLOCKS (ENC_ELEMS / (PREP_TB * 8))  // 6400

// ------------------------- persistent device scratch -------------------------
__device__ __align__(16) __half g_pmh[ENC_ELEMS];   // processed_memory fp16
__device__ __align__(16) __half g_ench[ENC_ELEMS];  // encoder outputs fp16

// fp16 weights, TRANSPOSED [K][O_pad]
__device__ __align__(16) __half g_tWp1[400 * 256];
__device__ __align__(16) __half g_tWp2[256 * 128];
__device__ __align__(16) __half g_tWaih[384 * 768];
__device__ __align__(16) __half g_tWahh[256 * 768];
__device__ __align__(16) __half g_tWq[256 * 256];
__device__ __align__(16) __half g_tWproj[512 * 256];
__device__ __align__(16) __half g_tWd1i[256 * 768];
__device__ __align__(16) __half g_tWd1h[256 * 768];
__device__ __align__(16) __half g_tWd2i[256 * 768];
__device__ __align__(16) __half g_tWd2h[256 * 768];
__device__ __align__(16) __half g_tWmel[256 * 512];   // O padded 400->512

// ------------------------- helpers -------------------------
__device__ __forceinline__ float tanh_approx(float x) {
    float y;
    asm("tanh.approx.f32 %0, %1;" : "=f"(y) : "f"(x));
    return y;
}
__device__ __forceinline__ float sigmoidf_(float x) {
    return 1.0f / (1.0f + __expf(-x));
}
__device__ __forceinline__ unsigned long long f2pack(float x, float y) {
    unsigned long long d;
    asm("mov.b64 %0, {%1, %2};" : "=l"(d) : "f"(x), "f"(y));
    return d;
}
__device__ __forceinline__ float2 f2unpack(unsigned long long v) {
    float2 r;
    asm("mov.b64 {%0, %1}, %2;" : "=f"(r.x), "=f"(r.y) : "l"(v));
    return r;
}
__device__ __forceinline__ unsigned long long ffma2(unsigned long long a,
                                                    unsigned long long b,
                                                    unsigned long long c) {
    unsigned long long d;
    asm("fma.rn.f32x2 %0, %1, %2, %3;" : "=l"(d) : "l"(a), "l"(b), "l"(c));
    return d;
}

// ------------------------- prep kernel ---------------------------------------
struct PrepArgs {
    const float* src[11];
    __half* dst[11];
    int O[11], K[11], OP[11];
    int start[12];
    const float* enc;
    const float* memW;
    __half* pm;
    __half* ench;
};

__global__ void __launch_bounds__(PREP_TB) prep_kernel(PrepArgs a) {
    int bid = blockIdx.x;
    if (bid < PM_BLOCKS) {
        __shared__ __align__(16) float se[PM_ROWS][DMODEL];
        size_t row0 = (size_t)bid * PM_ROWS;
        for (int i = threadIdx.x; i < PM_ROWS * DMODEL; i += PREP_TB)
            se[i >> 8][i & 255] = a.enc[row0 * DMODEL + i];
        __syncthreads();
        int o = threadIdx.x;
        float acc[PM_ROWS];
#pragma unroll
        for (int r = 0; r < PM_ROWS; ++r) acc[r] = 0.f;
        const float4* W4 = reinterpret_cast<const float4*>(a.memW + (size_t)o * DMODEL);
#pragma unroll 4
        for (int k4 = 0; k4 < DMODEL / 4; ++k4) {
            float4 w = __ldg(&W4[k4]);
#pragma unroll
            for (int r = 0; r < PM_ROWS; ++r) {
                const float* e = &se[r][k4 * 4];
                float s = acc[r];
                s = fmaf(w.x, e[0], s); s = fmaf(w.y, e[1], s);
                s = fmaf(w.z, e[2], s); s = fmaf(w.w, e[3], s);
                acc[r] = s;
            }
        }
#pragma unroll
        for (int r = 0; r < PM_ROWS; ++r)
            a.pm[(row0 + r) * DMODEL + o] = __float2half_rn(acc[r]);
        return;
    }
    int tb = bid - PM_BLOCKS;
    if (tb < a.start[11]) {
        int m = 0;
#pragma unroll
        for (int j = 0; j < 11; ++j)
            if (tb >= a.start[j + 1]) m = j + 1;
        int local = (tb - a.start[m]) * PREP_TB + threadIdx.x;
        int OP = a.OP[m], O = a.O[m], K = a.K[m];
        int k = local / OP, o = local - k * OP;
        __half v = (o < O) ? __float2half_rn(a.src[m][(size_t)o * K + k]) : __half(0.f);
        a.dst[m][local] = v;
        return;
    }
    // enc fp32 -> fp16
    int e = tb - a.start[11];
    size_t i0 = ((size_t)e * PREP_TB + threadIdx.x) * 8;
    const float4* S4 = reinterpret_cast<const float4*>(a.enc + i0);
    float4 f0 = S4[0], f1 = S4[1];
    __half2 h0 = __floats2half2_rn(f0.x, f0.y);
    __half2 h1 = __floats2half2_rn(f0.z, f0.w);
    __half2 h2 = __floats2half2_rn(f1.x, f1.y);
    __half2 h3 = __floats2half2_rn(f1.z, f1.w);
    uint4 outv;
    outv.x = *reinterpret_cast<uint32_t*>(&h0);
    outv.y = *reinterpret_cast<uint32_t*>(&h1);
    outv.z = *reinterpret_cast<uint32_t*>(&h2);
    outv.w = *reinterpret_cast<uint32_t*>(&h3);
    *reinterpret_cast<uint4*>(a.ench + i0) = outv;
}

// -------------- gemv task VEC=8 (one warp, 256 outputs, 2 rows) --------------
// WT [K][Ostride] fp16; x2[k]=(row0,row1); pp -> partial [2][256]
__device__ __forceinline__ void gemv_task8(const __half* __restrict__ WT, int Ostride,
                                           const float2* __restrict__ x2,
                                           int o0, int k0, int k1,
                                           float* __restrict__ pp) {
    const int lane = threadIdx.x & 31;
    const __half* base = WT + (size_t)k0 * Ostride + o0 + lane * 8;
    unsigned long long a0[4], a1[4];   // [pair] rows 0,1
#pragma unroll
    for (int j = 0; j < 4; ++j) { a0[j] = 0ull; a1[j] = 0ull; }
#pragma unroll 4
    for (int k = k0; k < k1; ++k) {
        uint4 wv = __ldg(reinterpret_cast<const uint4*>(base));
        base += Ostride;
        float2 f0 = __half22float2(*reinterpret_cast<__half2*>(&wv.x));
        float2 f1 = __half22float2(*reinterpret_cast<__half2*>(&wv.y));
        float2 f2 = __half22float2(*reinterpret_cast<__half2*>(&wv.z));
        float2 f3 = __half22float2(*reinterpret_cast<__half2*>(&wv.w));
        float2 xv = x2[k];
        unsigned long long xr0 = f2pack(xv.x, xv.x);
        unsigned long long xr1 = f2pack(xv.y, xv.y);
        unsigned long long w0 = f2pack(f0.x, f0.y);
        unsigned long long w1 = f2pack(f1.x, f1.y);
        unsigned long long w2 = f2pack(f2.x, f2.y);
        unsigned long long w3 = f2pack(f3.x, f3.y);
        a0[0] = ffma2(w0, xr0, a0[0]); a1[0] = ffma2(w0, xr1, a1[0]);
        a0[1] = ffma2(w1, xr0, a0[1]); a1[1] = ffma2(w1, xr1, a1[1]);
        a0[2] = ffma2(w2, xr0, a0[2]); a1[2] = ffma2(w2, xr1, a1[2]);
        a0[3] = ffma2(w3, xr0, a0[3]); a1[3] = ffma2(w3, xr1, a1[3]);
    }
    float2 t0, t1;
    float4 r;
    t0 = f2unpack(a0[0]); t1 = f2unpack(a0[1]);
    r = make_float4(t0.x, t0.y, t1.x, t1.y);
    reinterpret_cast<float4*>(pp)[lane * 2] = r;
    t0 = f2unpack(a0[2]); t1 = f2unpack(a0[3]);
    r = make_float4(t0.x, t0.y, t1.x, t1.y);
    reinterpret_cast<float4*>(pp)[lane * 2 + 1] = r;
    t0 = f2unpack(a1[0]); t1 = f2unpack(a1[1]);
    r = make_float4(t0.x, t0.y, t1.x, t1.y);
    reinterpret_cast<float4*>(pp + 256)[lane * 2] = r;
    t0 = f2unpack(a1[2]); t1 = f2unpack(a1[3]);
    r = make_float4(t0.x, t0.y, t1.x, t1.y);
    reinterpret_cast<float4*>(pp + 256)[lane * 2 + 1] = r;
}

// VEC8 partial reduce: tasks (o>>8)*NC + c starting at tb; task block = 512 floats
template <int NC>
__device__ __forceinline__ float redV8(const float* __restrict__ part, int tb,
                                       int o, int row) {
    const float* p = part + (size_t)(tb + (o >> 8) * NC) * 512 + row * 256 + (o & 255);
    float s = 0.f;
#pragma unroll
    for (int c = 0; c < NC; ++c) s += p[c * 512];
    return s;
}

// -------------- gemv task VEC=4 (128 outputs) for prenet2 --------------------
__device__ __forceinline__ void gemv_task4(const __half* __restrict__ WT, int Ostride,
                                           const float2* __restrict__ x2,
                                           int o0, int k0, int k1,
                                           float* __restrict__ pp) {
    const int lane = threadIdx.x & 31;
    const __half* base = WT + (size_t)k0 * Ostride + o0 + lane * 4;
    unsigned long long a0[2], a1[2];
    a0[0] = a0[1] = a1[0] = a1[1] = 0ull;
#pragma unroll 4
    for (int k = k0; k < k1; ++k) {
        uint2 wv = __ldg(reinterpret_cast<const uint2*>(base));
        base += Ostride;
        float2 w01 = __half22float2(*reinterpret_cast<__half2*>(&wv.x));
        float2 w23 = __half22float2(*reinterpret_cast<__half2*>(&wv.y));
        float2 xv = x2[k];
        unsigned long long xr0 = f2pack(xv.x, xv.x);
        unsigned long long xr1 = f2pack(xv.y, xv.y);
        unsigned long long wA = f2pack(w01.x, w01.y);
        unsigned long long wB = f2pack(w23.x, w23.y);
        a0[0] = ffma2(wA, xr0, a0[0]);
        a1[0] = ffma2(wA, xr1, a1[0]);
        a0[1] = ffma2(wB, xr0, a0[1]);
        a1[1] = ffma2(wB, xr1, a1[1]);
    }
    float2 p0 = f2unpack(a0[0]), p1 = f2unpack(a0[1]);
    float2 q0 = f2unpack(a1[0]), q1 = f2unpack(a1[1]);
    reinterpret_cast<float4*>(pp)[lane] = make_float4(p0.x, p0.y, p1.x, p1.y);
    reinterpret_cast<float4*>(pp + 128)[lane] = make_float4(q0.x, q0.y, q1.x, q1.y);
}

// VEC4 partial reduce: task block = 256 floats
template <int NC>
__device__ __forceinline__ float redV4(const float* __restrict__ part, int tb,
                                       int o, int row) {
    const float* p = part + (size_t)(tb + (o >> 7) * NC) * 256 + row * 128 + (o & 127);
    float s = 0.f;
#pragma unroll
    for (int c = 0; c < NC; ++c) s += p[c * 256];
    return s;
}

// ------------------------- shared memory layout ----------------------------
struct __align__(16) SD {
    float part[32 * 512];     // 64KB partials (also ctx scratch)
    float2 in2[400];
    float2 p12[256];
    float2 x2[384];           // [0:128)=prenet2, [128:384)=ctx
    float2 cat2[512];
    float2 d2[256];
    float2 ah2[256];
    float2 h12[256];
    float2 h22[256];
    float qT[2][256];
    float sc[2][TENC];
    float v[256];
    int len_s[2];
    float b_p1[256]; float b_p2[128];
    float b_aih[768]; float b_ahh[768];
    float b_proj[256];
    float b_d1i[768]; float b_d1h[768];
    float b_d2i[768]; float b_d2h[768];
    float b_mel[400];
};

// ------------------------- main persistent decoder -------------------------
__global__ void __launch_bounds__(TB, 1) decoder_kernel(
    const float* __restrict__ inputs,
    const int* __restrict__ memlen,
    const float* __restrict__ gb_p1, const float* __restrict__ gb_p2,
    const float* __restrict__ gb_aih, const float* __restrict__ gb_ahh,
    const float* __restrict__ vW,
    const float* __restrict__ gb_proj,
    const float* __restrict__ gb_d1i, const float* __restrict__ gb_d1h,
    const float* __restrict__ gb_d2i, const float* __restrict__ gb_d2h,
    const float* __restrict__ gb_mel,
    float* __restrict__ out, int write_align) {
    extern __shared__ unsigned char smem_raw[];
    SD* s = reinterpret_cast<SD*>(smem_raw);

    const int tid = threadIdx.x;
    const int wid = tid >> 5;
    const int lane = tid & 31;
    const int b0 = blockIdx.x * ROWS;

    // init state + biases
    {
        float2 z2 = make_float2(0.f, 0.f);
        if (tid < 256) {
            s->ah2[tid] = z2; s->h12[tid] = z2; s->h22[tid] = z2;
            s->x2[128 + tid] = z2;
            s->v[tid] = vW[tid];
            s->b_p1[tid] = gb_p1[tid];
            s->b_proj[tid] = gb_proj[tid];
        }
        if (tid >= 256 && tid < 384) s->b_p2[tid - 256] = gb_p2[tid - 256];
        if (tid < 768) {
            s->b_aih[tid] = gb_aih[tid]; s->b_ahh[tid] = gb_ahh[tid];
            s->b_d1i[tid] = gb_d1i[tid]; s->b_d1h[tid] = gb_d1h[tid];
            s->b_d2i[tid] = gb_d2i[tid]; s->b_d2h[tid] = gb_d2h[tid];
        }
        if (tid >= 512 && tid < 912) s->b_mel[tid - 512] = gb_mel[tid - 512];
        if (tid < 2) s->len_s[tid] = memlen[b0 + tid];
    }
    __syncthreads();

    float* outMel = out;
    float* outAl = out + (size_t)BATCH * TD * INR;

    for (int t = 0; t < TD; ++t) {
        // ---- teacher-forced input ----
        if (t == 0) {
            if (tid < 2 * INR) {
                int row = tid / INR, o = tid - row * INR;
                reinterpret_cast<float*>(&s->in2[o])[row] = 0.f;
            }
        } else {
            if (tid < 2 * INR) {
                int row = tid / INR, o = tid - row * INR;
                reinterpret_cast<float*>(&s->in2[o])[row] =
                    inputs[((size_t)(b0 + row) * 1000 + (size_t)(t - 1) * 5) * 80 + o];
            }
        }
        __syncthreads();

        // ---- A: prenet1 (O=256,K=400): 32 k-chunks of 12/13 ----
        {
            int c = wid;
            gemv_task8(g_tWp1, 256, s->in2, 0, (c * 25) >> 1, ((c + 1) * 25) >> 1,
                       s->part + (size_t)wid * 512);
        }
        __syncthreads();
        if (tid < 512) {
            int o = tid & 255, row = tid >> 8;
            float r = redV8<32>(s->part, 0, o, row) + s->b_p1[o];
            reinterpret_cast<float*>(&s->p12[o])[row] = fmaxf(r, 0.f);
        }
        __syncthreads();

        // ---- B: prenet2 (O=128,K=256): VEC4, 32 chunks CH=8 ----
        {
            gemv_task4(g_tWp2, 128, s->p12, 0, wid * 8, wid * 8 + 8,
                       s->part + (size_t)wid * 256);
        }
        __syncthreads();
        if (tid < 256) {
            int o = tid & 127, row = tid >> 7;
            float r = redV4<32>(s->part, 0, o, row) + s->b_p2[o];
            reinterpret_cast<float*>(&s->x2[o])[row] = fmaxf(r, 0.f);
        }
        __syncthreads();

        // ---- C: attn GRU: gi 18 tasks (3x6,CH=64) + gh 12 tasks (3x4,CH=64) ----
        for (int task = wid; task < 30; task += 32) {
            if (task < 18) {
                int ot = task / 6, c = task - ot * 6;
                gemv_task8(g_tWaih, 768, s->x2, ot * 256, c * 64, c * 64 + 64,
                           s->part + (size_t)task * 512);
            } else {
                int t2 = task - 18;
                int ot = t2 >> 2, c = t2 & 3;
                gemv_task8(g_tWahh, 768, s->ah2, ot * 256, c * 64, c * 64 + 64,
                           s->part + (size_t)task * 512);
            }
        }
        __syncthreads();
        if (tid < 512) {
            int o = tid & 255, row = tid >> 8;
            float ir = redV8<6>(s->part, 0, o, row) + s->b_aih[o];
            float iz = redV8<6>(s->part, 0, 256 + o, row) + s->b_aih[256 + o];
            float in = redV8<6>(s->part, 0, 512 + o, row) + s->b_aih[512 + o];
            float hr = redV8<4>(s->part, 18, o, row) + s->b_ahh[o];
            float hz = redV8<4>(s->part, 18, 256 + o, row) + s->b_ahh[256 + o];
            float hn = redV8<4>(s->part, 18, 512 + o, row) + s->b_ahh[512 + o];
            float hp = reinterpret_cast<float*>(&s->ah2[o])[row];
            float rg = sigmoidf_(ir + hr);
            float z = sigmoidf_(iz + hz);
            float n = tanhf(in + rg * hn);
            float h = (1.f - z) * n + z * hp;
            reinterpret_cast<float*>(&s->ah2[o])[row] = h;
            reinterpret_cast<float*>(&s->cat2[o])[row] = h;
        }
        __syncthreads();

        // ---- D: query (O=256,K=256): 32 chunks CH=8 ----
        {
            gemv_task8(g_tWq, 256, s->ah2, 0, wid * 8, wid * 8 + 8,
                       s->part + (size_t)wid * 512);
        }
        __syncthreads();
        if (tid < 512) {
            int o = tid & 255, row = tid >> 8;
            s->qT[row][o] = redV8<32>(s->part, 0, o, row);
        }
        __syncthreads();

        // ---- E: Bahdanau scores (fp16 pm) ----
        for (int task = wid; task < 2 * TENC; task += 32) {
            int row = task & 1, tt = task >> 1;
            const uint4* P = reinterpret_cast<const uint4*>(
                g_pmh + ((size_t)(b0 + row) * TENC + tt) * DMODEL);
            uint4 pv = __ldg(&P[lane]);
            float2 p0 = __half22float2(*reinterpret_cast<__half2*>(&pv.x));
            float2 p1 = __half22float2(*reinterpret_cast<__half2*>(&pv.y));
            float2 p2 = __half22float2(*reinterpret_cast<__half2*>(&pv.z));
            float2 p3 = __half22float2(*reinterpret_cast<__half2*>(&pv.w));
            const float4* Q = reinterpret_cast<const float4*>(s->qT[row]);
            const float4* V = reinterpret_cast<const float4*>(s->v);
            float4 q0 = Q[lane * 2], q1 = Q[lane * 2 + 1];
            float4 v0 = V[lane * 2], v1 = V[lane * 2 + 1];
            float acc = 0.f;
            acc += v0.x * tanh_approx(p0.x + q0.x);
            acc += v0.y * tanh_approx(p0.y + q0.y);
            acc += v0.z * tanh_approx(p1.x + q0.z);
            acc += v0.w * tanh_approx(p1.y + q0.w);
            acc += v1.x * tanh_approx(p2.x + q1.x);
            acc += v1.y * tanh_approx(p2.y + q1.y);
            acc += v1.z * tanh_approx(p3.x + q1.z);
            acc += v1.w * tanh_approx(p3.y + q1.w);
#pragma unroll
            for (int sh = 16; sh; sh >>= 1) acc += __shfl_xor_sync(0xffffffffu, acc, sh);
            if (lane == 0)
                s->sc[row][tt] = (tt < s->len_s[row]) ? acc : -1e9f;
        }
        __syncthreads();

        // ---- F: softmax per row (warps 0..1) + alignment output ----
        if (wid < 2) {
            int row = wid;
            float m = -1e30f;
            for (int i = lane; i < TENC; i += 32) m = fmaxf(m, s->sc[row][i]);
#pragma unroll
            for (int sh = 16; sh; sh >>= 1) m = fmaxf(m, __shfl_xor_sync(0xffffffffu, m, sh));
            float sum = 0.f;
            for (int i = lane; i < TENC; i += 32) {
                float e = __expf(s->sc[row][i] - m);
                s->sc[row][i] = e;
                sum += e;
            }
#pragma unroll
            for (int sh = 16; sh; sh >>= 1) sum += __shfl_xor_sync(0xffffffffu, sum, sh);
            float inv = 1.f / sum;
            float* ao = outAl + ((size_t)(b0 + row) * TD + t) * TENC;
            for (int i = lane; i < TENC; i += 32) {
                float a = s->sc[row][i] * inv;
                s->sc[row][i] = a;
                if (write_align) ao[i] = a;
            }
        }
        __syncthreads();

        // ---- G: attention context (fp16 enc): g(64) x row(2) x ts(8x25) ----
        {
            int g = tid & 63, row = (tid >> 6) & 1, ts = tid >> 7;
            const uint2* E = reinterpret_cast<const uint2*>(
                                 g_ench + (size_t)(b0 + row) * TENC * DMODEL);
            const float* scp = s->sc[row];
            float4 acc = make_float4(0.f, 0.f, 0.f, 0.f);
            int tt0 = ts * 25;
#pragma unroll 5
            for (int tt = tt0; tt < tt0 + 25; ++tt) {
                float a = scp[tt];
                uint2 ev = __ldg(&E[tt * 64 + g]);
                float2 e0 = __half22float2(*reinterpret_cast<__half2*>(&ev.x));
                float2 e1 = __half22float2(*reinterpret_cast<__half2*>(&ev.y));
                acc.x = fmaf(a, e0.x, acc.x);
                acc.y = fmaf(a, e0.y, acc.y);
                acc.z = fmaf(a, e1.x, acc.z);
                acc.w = fmaf(a, e1.y, acc.w);
            }
            reinterpret_cast<float4*>(s->part)[(ts * 2 + row) * 64 + g] = acc;
        }
        __syncthreads();
        if (tid < 512) {
            int o = tid & 255, row = tid >> 8;
            int gg = o >> 2, comp = o & 3;
            const float* pf = s->part;
            float sv = 0.f;
#pragma unroll
            for (int ts = 0; ts < 8; ++ts)
                sv += pf[((ts * 2 + row) * 64 + gg) * 4 + comp];
            reinterpret_cast<float*>(&s->x2[128 + o])[row] = sv;
            reinterpret_cast<float*>(&s->cat2[256 + o])[row] = sv;
        }
        __syncthreads();

        // ---- H: proj (O=256,K=512): 32 chunks CH=16 ----
        {
            gemv_task8(g_tWproj, 256, s->cat2, 0, wid * 16, wid * 16 + 16,
                       s->part + (size_t)wid * 512);
        }
        __syncthreads();
        if (tid < 512) {
            int o = tid & 255, row = tid >> 8;
            float r = redV8<32>(s->part, 0, o, row) + s->b_proj[o];
            reinterpret_cast<float*>(&s->d2[o])[row] = r;
        }
        __syncthreads();

        // ---- I/J: decoder GRUs: gi 15 tasks (3x5) + gh 15 tasks (3x5) ----
#pragma unroll
        for (int gru = 0; gru < 2; ++gru) {
            const __half* Wi = gru ? g_tWd2i : g_tWd1i;
            const __half* Wh = gru ? g_tWd2h : g_tWd1h;
            const float* bi = gru ? s->b_d2i : s->b_d1i;
            const float* bh = gru ? s->b_d2h : s->b_d1h;
            float2* hstate = gru ? s->h22 : s->h12;
            for (int task = wid; task < 30; task += 32) {
                if (task < 15) {
                    int ot = task / 5, c = task - ot * 5;
                    gemv_task8(Wi, 768, s->d2, ot * 256,
                               (c * 256) / 5, ((c + 1) * 256) / 5,
                               s->part + (size_t)task * 512);
                } else {
                    int t2 = task - 15;
                    int ot = t2 / 5, c = t2 - ot * 5;
                    gemv_task8(Wh, 768, hstate, ot * 256,
                               (c * 256) / 5, ((c + 1) * 256) / 5,
                               s->part + (size_t)task * 512);
                }
            }
            __syncthreads();
            if (tid < 512) {
                int o = tid & 255, row = tid >> 8;
                float ir = redV8<5>(s->part, 0, o, row) + bi[o];
                float iz = redV8<5>(s->part, 0, 256 + o, row) + bi[256 + o];
                float in = redV8<5>(s->part, 0, 512 + o, row) + bi[512 + o];
                float hr = redV8<5>(s->part, 15, o, row) + bh[o];
                float hz = redV8<5>(s->part, 15, 256 + o, row) + bh[256 + o];
                float hn = redV8<5>(s->part, 15, 512 + o, row) + bh[512 + o];
                float hp = reinterpret_cast<float*>(&hstate[o])[row];
                float rg = sigmoidf_(ir + hr);
                float z = sigmoidf_(iz + hz);
                float n = tanhf(in + rg * hn);
                float h = (1.f - z) * n + z * hp;
                reinterpret_cast<float*>(&hstate[o])[row] = h;
                reinterpret_cast<float*>(&s->d2[o])[row] += h;
            }
            __syncthreads();
        }

        // ---- K: mel (O=512 pad, K=256): 2 tiles x 16 chunks CH=16 ----
        {
            int ot = wid >> 4, c = wid & 15;
            gemv_task8(g_tWmel, 512, s->d2, ot * 256, c * 16, c * 16 + 16,
                       s->part + (size_t)wid * 512);
        }
        __syncthreads();
        if (tid < 2 * INR) {
            int row = tid / INR, o = tid - row * INR;
            float r = redV8<16>(s->part, 0, o, row) + s->b_mel[o];
            outMel[((size_t)(b0 + row) * TD + t) * INR + o] = r;
        }
        __syncthreads();
    }
}

// ------------------------- launch -------------------------
extern "C" void kernel_launch(void* const* d_in, const int* in_sizes, int n_in,
                              void* d_out, int out_size) {
    const float* enc = (const float*)d_in[0];
    const float* inputs = (const float*)d_in[1];
    const int* memlen = (const int*)d_in[2];

    PrepArgs a;
    static const int srcIdx[11] = {3, 5, 7, 9, 12, 14, 16, 18, 20, 22, 24};
    static const int Oarr[11] = {256, 128, 768, 768, 256, 256, 768, 768, 768, 768, 400};
    static const int Karr[11] = {400, 256, 384, 256, 256, 512, 256, 256, 256, 256, 256};
    static const int OParr[11] = {256, 128, 768, 768, 256, 256, 768, 768, 768, 768, 512};

    void* dsts[11];
    cudaGetSymbolAddress(&dsts[0], g_tWp1);
    cudaGetSymbolAddress(&dsts[1], g_tWp2);
    cudaGetSymbolAddress(&dsts[2], g_tWaih);
    cudaGetSymbolAddress(&dsts[3], g_tWahh);
    cudaGetSymbolAddress(&dsts[4], g_tWq);
    cudaGetSymbolAddress(&dsts[5], g_tWproj);
    cudaGetSymbolAddress(&dsts[6], g_tWd1i);
    cudaGetSymbolAddress(&dsts[7], g_tWd1h);
    cudaGetSymbolAddress(&dsts[8], g_tWd2i);
    cudaGetSymbolAddress(&dsts[9], g_tWd2h);
    cudaGetSymbolAddress(&dsts[10], g_tWmel);

    int cum = 0;
    for (int m = 0; m < 11; ++m) {
        a.src[m] = (const float*)d_in[srcIdx[m]];
        a.dst[m] = (__half*)dsts[m];
        a.O[m] = Oarr[m]; a.K[m] = Karr[m]; a.OP[m] = OParr[m];
        a.start[m] = cum;
        cum += (Karr[m] * OParr[m]) / PREP_TB;
    }
    a.start[11] = cum;   // 6800
    a.enc = enc;
    a.memW = (const float*)d_in[11];
    cudaGetSymbolAddress((void**)&a.pm, g_pmh);
    cudaGetSymbolAddress((void**)&a.ench, g_ench);

    prep_kernel<<<PM_BLOCKS + cum + ENC_CVT_BLOCKS, PREP_TB>>>(a);

    static bool attr_done = false;
    if (!attr_done) {
        cudaFuncSetAttribute(decoder_kernel,
                             cudaFuncAttributeMaxDynamicSharedMemorySize,
                             (int)sizeof(SD));
        attr_done = true;
    }

    int write_align = (out_size >= BATCH * TD * (INR + TENC)) ? 1 : 0;

    decoder_kernel<<<NGROUPS, TB, sizeof(SD)>>>(
        inputs, memlen,
        (const float*)d_in[4], (const float*)d_in[6],
        (const float*)d_in[8], (const float*)d_in[10],
        (const float*)d_in[13],
        (const float*)d_in[15],
        (const float*)d_in[17], (const float*)d_in[19],
        (const float*)d_in[21], (const float*)d_in[23],
        (const float*)d_in[25],
        (float*)d_out, write_align);
}

// round 10
// speedup vs baseline: 4.9079x; 1.0028x over previous
#include <cuda_runtime.h>
#include <cuda_fp16.h>
#include <cstdint>
#include <cstddef>

#define TB 1024
#define PREP_TB 256
#define BATCH 256
#define ROWS 2
#define NGROUPS (BATCH / ROWS)       // 128 CTAs
#define TENC 200
#define TD 200
#define DMODEL 256
#define INR 400
#define PM_ROWS 16
#define PM_BLOCKS (BATCH * TENC / PM_ROWS)          // 3200
#define ENC_ELEMS (BATCH * TENC * DMODEL)           // 13107200
#define ENC_CVT_BLOCKS (ENC_ELEMS / (PREP_TB * 8))  // 6400

// ------------------------- persistent device scratch -------------------------
__device__ __align__(16) __half g_pmh[ENC_ELEMS];   // processed_memory fp16
__device__ __align__(16) __half g_ench[ENC_ELEMS];  // encoder outputs fp16

// fp16 weights, TRANSPOSED [K][O_pad]
__device__ __align__(16) __half g_tWp1[400 * 256];
__device__ __align__(16) __half g_tWp2[256 * 128];
__device__ __align__(16) __half g_tWaih[384 * 768];
__device__ __align__(16) __half g_tWahh[256 * 768];
__device__ __align__(16) __half g_tWq[256 * 256];
__device__ __align__(16) __half g_tWproj[512 * 256];
__device__ __align__(16) __half g_tWd1i[256 * 768];
__device__ __align__(16) __half g_tWd1h[256 * 768];
__device__ __align__(16) __half g_tWd2i[256 * 768];
__device__ __align__(16) __half g_tWd2h[256 * 768];
__device__ __align__(16) __half g_tWmel[256 * 512];   // O padded 400->512

// ------------------------- helpers -------------------------
__device__ __forceinline__ float tanh_approx(float x) {
    float y;
    asm("tanh.approx.f32 %0, %1;" : "=f"(y) : "f"(x));
    return y;
}
__device__ __forceinline__ float sigmoidf_(float x) {
    return 1.0f / (1.0f + __expf(-x));
}
__device__ __forceinline__ unsigned long long f2pack(float x, float y) {
    unsigned long long d;
    asm("mov.b64 %0, {%1, %2};" : "=l"(d) : "f"(x), "f"(y));
    return d;
}
__device__ __forceinline__ float2 f2unpack(unsigned long long v) {
    float2 r;
    asm("mov.b64 {%0, %1}, %2;" : "=f"(r.x), "=f"(r.y) : "l"(v));
    return r;
}
__device__ __forceinline__ unsigned long long ffma2(unsigned long long a,
                                                    unsigned long long b,
                                                    unsigned long long c) {
    unsigned long long d;
    asm("fma.rn.f32x2 %0, %1, %2, %3;" : "=l"(d) : "l"(a), "l"(b), "l"(c));
    return d;
}
// prefetch 8 k-rows x 512B of a weight tile into L1 (one instr per thread)
__device__ __forceinline__ void pfw(const __half* WT, int Ostride, int o0, int k0) {
    int lane = threadIdx.x & 31;
    const __half* p = WT + (size_t)(k0 + (lane >> 2)) * Ostride + o0 + (lane & 3) * 64;
    asm volatile("prefetch.global.L1 [%0];" :: "l"(p));
}
__device__ __forceinline__ void pf_raw(const void* p) {
    asm volatile("prefetch.global.L1 [%0];" :: "l"(p));
}

// ------------------------- prep kernel ---------------------------------------
struct PrepArgs {
    const float* src[11];
    __half* dst[11];
    int O[11], K[11], OP[11];
    int start[12];
    const float* enc;
    const float* memW;
    __half* pm;
    __half* ench;
};

__global__ void __launch_bounds__(PREP_TB) prep_kernel(PrepArgs a) {
    int bid = blockIdx.x;
    if (bid < PM_BLOCKS) {
        __shared__ __align__(16) float se[PM_ROWS][DMODEL];
        size_t row0 = (size_t)bid * PM_ROWS;
        for (int i = threadIdx.x; i < PM_ROWS * DMODEL; i += PREP_TB)
            se[i >> 8][i & 255] = a.enc[row0 * DMODEL + i];
        __syncthreads();
        int o = threadIdx.x;
        float acc[PM_ROWS];
#pragma unroll
        for (int r = 0; r < PM_ROWS; ++r) acc[r] = 0.f;
        const float4* W4 = reinterpret_cast<const float4*>(a.memW + (size_t)o * DMODEL);
#pragma unroll 4
        for (int k4 = 0; k4 < DMODEL / 4; ++k4) {
            float4 w = __ldg(&W4[k4]);
#pragma unroll
            for (int r = 0; r < PM_ROWS; ++r) {
                const float* e = &se[r][k4 * 4];
                float s = acc[r];
                s = fmaf(w.x, e[0], s); s = fmaf(w.y, e[1], s);
                s = fmaf(w.z, e[2], s); s = fmaf(w.w, e[3], s);
                acc[r] = s;
            }
        }
#pragma unroll
        for (int r = 0; r < PM_ROWS; ++r)
            a.pm[(row0 + r) * DMODEL + o] = __float2half_rn(acc[r]);
        return;
    }
    int tb = bid - PM_BLOCKS;
    if (tb < a.start[11]) {
        int m = 0;
#pragma unroll
        for (int j = 0; j < 11; ++j)
            if (tb >= a.start[j + 1]) m = j + 1;
        int local = (tb - a.start[m]) * PREP_TB + threadIdx.x;
        int OP = a.OP[m], O = a.O[m], K = a.K[m];
        int k = local / OP, o = local - k * OP;
        __half v = (o < O) ? __float2half_rn(a.src[m][(size_t)o * K + k]) : __half(0.f);
        a.dst[m][local] = v;
        return;
    }
    // enc fp32 -> fp16
    int e = tb - a.start[11];
    size_t i0 = ((size_t)e * PREP_TB + threadIdx.x) * 8;
    const float4* S4 = reinterpret_cast<const float4*>(a.enc + i0);
    float4 f0 = S4[0], f1 = S4[1];
    __half2 h0 = __floats2half2_rn(f0.x, f0.y);
    __half2 h1 = __floats2half2_rn(f0.z, f0.w);
    __half2 h2 = __floats2half2_rn(f1.x, f1.y);
    __half2 h3 = __floats2half2_rn(f1.z, f1.w);
    uint4 outv;
    outv.x = *reinterpret_cast<uint32_t*>(&h0);
    outv.y = *reinterpret_cast<uint32_t*>(&h1);
    outv.z = *reinterpret_cast<uint32_t*>(&h2);
    outv.w = *reinterpret_cast<uint32_t*>(&h3);
    *reinterpret_cast<uint4*>(a.ench + i0) = outv;
}

// -------------- gemv task VEC=8 (one warp, 256 outputs, 2 rows) --------------
__device__ __forceinline__ void gemv_task8(const __half* __restrict__ WT, int Ostride,
                                           const float2* __restrict__ x2,
                                           int o0, int k0, int k1,
                                           float* __restrict__ pp) {
    const int lane = threadIdx.x & 31;
    const __half* base = WT + (size_t)k0 * Ostride + o0 + lane * 8;
    unsigned long long a0[4], a1[4];
#pragma unroll
    for (int j = 0; j < 4; ++j) { a0[j] = 0ull; a1[j] = 0ull; }
#pragma unroll 4
    for (int k = k0; k < k1; ++k) {
        uint4 wv = __ldg(reinterpret_cast<const uint4*>(base));
        base += Ostride;
        float2 f0 = __half22float2(*reinterpret_cast<__half2*>(&wv.x));
        float2 f1 = __half22float2(*reinterpret_cast<__half2*>(&wv.y));
        float2 f2 = __half22float2(*reinterpret_cast<__half2*>(&wv.z));
        float2 f3 = __half22float2(*reinterpret_cast<__half2*>(&wv.w));
        float2 xv = x2[k];
        unsigned long long xr0 = f2pack(xv.x, xv.x);
        unsigned long long xr1 = f2pack(xv.y, xv.y);
        unsigned long long w0 = f2pack(f0.x, f0.y);
        unsigned long long w1 = f2pack(f1.x, f1.y);
        unsigned long long w2 = f2pack(f2.x, f2.y);
        unsigned long long w3 = f2pack(f3.x, f3.y);
        a0[0] = ffma2(w0, xr0, a0[0]); a1[0] = ffma2(w0, xr1, a1[0]);
        a0[1] = ffma2(w1, xr0, a0[1]); a1[1] = ffma2(w1, xr1, a1[1]);
        a0[2] = ffma2(w2, xr0, a0[2]); a1[2] = ffma2(w2, xr1, a1[2]);
        a0[3] = ffma2(w3, xr0, a0[3]); a1[3] = ffma2(w3, xr1, a1[3]);
    }
    float2 t0, t1;
    float4 r;
    t0 = f2unpack(a0[0]); t1 = f2unpack(a0[1]);
    r = make_float4(t0.x, t0.y, t1.x, t1.y);
    reinterpret_cast<float4*>(pp)[lane * 2] = r;
    t0 = f2unpack(a0[2]); t1 = f2unpack(a0[3]);
    r = make_float4(t0.x, t0.y, t1.x, t1.y);
    reinterpret_cast<float4*>(pp)[lane * 2 + 1] = r;
    t0 = f2unpack(a1[0]); t1 = f2unpack(a1[1]);
    r = make_float4(t0.x, t0.y, t1.x, t1.y);
    reinterpret_cast<float4*>(pp + 256)[lane * 2] = r;
    t0 = f2unpack(a1[2]); t1 = f2unpack(a1[3]);
    r = make_float4(t0.x, t0.y, t1.x, t1.y);
    reinterpret_cast<float4*>(pp + 256)[lane * 2 + 1] = r;
}

// VEC8 partial reduce: tasks (o>>8)*NC + c starting at tb; task block = 512 floats
template <int NC>
__device__ __forceinline__ float redV8(const float* __restrict__ part, int tb,
                                       int o, int row) {
    const float* p = part + (size_t)(tb + (o >> 8) * NC) * 512 + row * 256 + (o & 255);
    float s = 0.f;
#pragma unroll
    for (int c = 0; c < NC; ++c) s += p[c * 512];
    return s;
}

// -------------- gemv task VEC=4 (128 outputs) for prenet2 --------------------
__device__ __forceinline__ void gemv_task4(const __half* __restrict__ WT, int Ostride,
                                           const float2* __restrict__ x2,
                                           int o0, int k0, int k1,
                                           float* __restrict__ pp) {
    const int lane = threadIdx.x & 31;
    const __half* base = WT + (size_t)k0 * Ostride + o0 + lane * 4;
    unsigned long long a0[2], a1[2];
    a0[0] = a0[1] = a1[0] = a1[1] = 0ull;
#pragma unroll 4
    for (int k = k0; k < k1; ++k) {
        uint2 wv = __ldg(reinterpret_cast<const uint2*>(base));
        base += Ostride;
        float2 w01 = __half22float2(*reinterpret_cast<__half2*>(&wv.x));
        float2 w23 = __half22float2(*reinterpret_cast<__half2*>(&wv.y));
        float2 xv = x2[k];
        unsigned long long xr0 = f2pack(xv.x, xv.x);
        unsigned long long xr1 = f2pack(xv.y, xv.y);
        unsigned long long wA = f2pack(w01.x, w01.y);
        unsigned long long wB = f2pack(w23.x, w23.y);
        a0[0] = ffma2(wA, xr0, a0[0]);
        a1[0] = ffma2(wA, xr1, a1[0]);
        a0[1] = ffma2(wB, xr0, a0[1]);
        a1[1] = ffma2(wB, xr1, a1[1]);
    }
    float2 p0 = f2unpack(a0[0]), p1 = f2unpack(a0[1]);
    float2 q0 = f2unpack(a1[0]), q1 = f2unpack(a1[1]);
    reinterpret_cast<float4*>(pp)[lane] = make_float4(p0.x, p0.y, p1.x, p1.y);
    reinterpret_cast<float4*>(pp + 128)[lane] = make_float4(q0.x, q0.y, q1.x, q1.y);
}

// VEC4 partial reduce: task block = 256 floats
template <int NC>
__device__ __forceinline__ float redV4(const float* __restrict__ part, int tb,
                                       int o, int row) {
    const float* p = part + (size_t)(tb + (o >> 7) * NC) * 256 + row * 128 + (o & 127);
    float s = 0.f;
#pragma unroll
    for (int c = 0; c < NC; ++c) s += p[c * 256];
    return s;
}

// ------------------------- shared memory layout ----------------------------
struct __align__(16) SD {
    float part[32 * 512];     // 64KB partials (also ctx scratch)
    float2 in2[400];
    float2 p12[256];
    float2 x2[384];           // [0:128)=prenet2, [128:384)=ctx
    float2 cat2[512];
    float2 d2[256];
    float2 ah2[256];
    float2 h12[256];
    float2 h22[256];
    float qT[2][256];
    float sc[2][TENC];
    float v[256];
    int len_s[2];
    float b_p1[256]; float b_p2[128];
    float b_aih[768]; float b_ahh[768];
    float b_proj[256];
    float b_d1i[768]; float b_d1h[768];
    float b_d2i[768]; float b_d2h[768];
    float b_mel[400];
};

// ------------------------- main persistent decoder -------------------------
__global__ void __launch_bounds__(TB, 1) decoder_kernel(
    const float* __restrict__ inputs,
    const int* __restrict__ memlen,
    const float* __restrict__ gb_p1, const float* __restrict__ gb_p2,
    const float* __restrict__ gb_aih, const float* __restrict__ gb_ahh,
    const float* __restrict__ vW,
    const float* __restrict__ gb_proj,
    const float* __restrict__ gb_d1i, const float* __restrict__ gb_d1h,
    const float* __restrict__ gb_d2i, const float* __restrict__ gb_d2h,
    const float* __restrict__ gb_mel,
    float* __restrict__ out, int write_align) {
    extern __shared__ unsigned char smem_raw[];
    SD* s = reinterpret_cast<SD*>(smem_raw);

    const int tid = threadIdx.x;
    const int wid = tid >> 5;
    const int lane = tid & 31;
    const int b0 = blockIdx.x * ROWS;

    // init state + biases + zero first input
    {
        float2 z2 = make_float2(0.f, 0.f);
        if (tid < 256) {
            s->ah2[tid] = z2; s->h12[tid] = z2; s->h22[tid] = z2;
            s->x2[128 + tid] = z2;
            s->v[tid] = vW[tid];
            s->b_p1[tid] = gb_p1[tid];
            s->b_proj[tid] = gb_proj[tid];
        }
        if (tid >= 256 && tid < 384) s->b_p2[tid - 256] = gb_p2[tid - 256];
        if (tid < 768) {
            s->b_aih[tid] = gb_aih[tid]; s->b_ahh[tid] = gb_ahh[tid];
            s->b_d1i[tid] = gb_d1i[tid]; s->b_d1h[tid] = gb_d1h[tid];
            s->b_d2i[tid] = gb_d2i[tid]; s->b_d2h[tid] = gb_d2h[tid];
        }
        if (tid >= 512 && tid < 912) s->b_mel[tid - 512] = gb_mel[tid - 512];
        if (tid < 2) s->len_s[tid] = memlen[b0 + tid];
        if (tid < 400) s->in2[tid] = z2;   // teacher input at t=0 is zeros
    }
    __syncthreads();

    float* outMel = out;
    float* outAl = out + (size_t)BATCH * TD * INR;

    for (int t = 0; t < TD; ++t) {
        // ---- A: prenet1 (O=256,K=400): 32 k-chunks of 12/13 ----
        {
            int c = wid;
            gemv_task8(g_tWp1, 256, s->in2, 0, (c * 25) >> 1, ((c + 1) * 25) >> 1,
                       s->part + (size_t)wid * 512);
            pfw(g_tWp2, 128, 0, wid * 8);              // prefetch B
        }
        __syncthreads();
        if (tid < 512) {
            int o = tid & 255, row = tid >> 8;
            float r = redV8<32>(s->part, 0, o, row) + s->b_p1[o];
            reinterpret_cast<float*>(&s->p12[o])[row] = fmaxf(r, 0.f);
        } else if (t + 1 < TD) {
            // load teacher-forced input for NEXT step (in2 no longer read this step)
            for (int i = tid - 512; i < 2 * INR; i += 512) {
                int row = i / INR, o = i - row * INR;
                reinterpret_cast<float*>(&s->in2[o])[row] =
                    inputs[((size_t)(b0 + row) * 1000 + (size_t)t * 5) * 80 + o];
            }
        }
        __syncthreads();

        // ---- B: prenet2 (O=128,K=256): VEC4, 32 chunks CH=8 ----
        {
            gemv_task4(g_tWp2, 128, s->p12, 0, wid * 8, wid * 8 + 8,
                       s->part + (size_t)wid * 256);
            // prefetch C (attn GRU) weights for this warp's task
            if (wid < 18) pfw(g_tWaih, 768, (wid / 6) * 256, (wid % 6) * 64);
            else if (wid < 30) { int t2 = wid - 18; pfw(g_tWahh, 768, (t2 >> 2) * 256, (t2 & 3) * 64); }
            else pfw(g_tWq, 256, 0, (wid & 15) * 8);
        }
        __syncthreads();
        if (tid < 256) {
            int o = tid & 127, row = tid >> 7;
            float r = redV4<32>(s->part, 0, o, row) + s->b_p2[o];
            reinterpret_cast<float*>(&s->x2[o])[row] = fmaxf(r, 0.f);
        }
        __syncthreads();

        // ---- C: attn GRU: gi 18 tasks (3x6,CH=64) + gh 12 tasks (3x4,CH=64) ----
        for (int task = wid; task < 30; task += 32) {
            if (task < 18) {
                int ot = task / 6, c = task - ot * 6;
                gemv_task8(g_tWaih, 768, s->x2, ot * 256, c * 64, c * 64 + 64,
                           s->part + (size_t)task * 512);
            } else {
                int t2 = task - 18;
                int ot = t2 >> 2, c = t2 & 3;
                gemv_task8(g_tWahh, 768, s->ah2, ot * 256, c * 64, c * 64 + 64,
                           s->part + (size_t)task * 512);
            }
        }
        pfw(g_tWq, 256, 0, wid * 8);                   // prefetch D
        __syncthreads();
        if (tid < 512) {
            int o = tid & 255, row = tid >> 8;
            float ir = redV8<6>(s->part, 0, o, row) + s->b_aih[o];
            float iz = redV8<6>(s->part, 0, 256 + o, row) + s->b_aih[256 + o];
            float in = redV8<6>(s->part, 0, 512 + o, row) + s->b_aih[512 + o];
            float hr = redV8<4>(s->part, 18, o, row) + s->b_ahh[o];
            float hz = redV8<4>(s->part, 18, 256 + o, row) + s->b_ahh[256 + o];
            float hn = redV8<4>(s->part, 18, 512 + o, row) + s->b_ahh[512 + o];
            float hp = reinterpret_cast<float*>(&s->ah2[o])[row];
            float rg = sigmoidf_(ir + hr);
            float z = sigmoidf_(iz + hz);
            float n = tanhf(in + rg * hn);
            float h = (1.f - z) * n + z * hp;
            reinterpret_cast<float*>(&s->ah2[o])[row] = h;
            reinterpret_cast<float*>(&s->cat2[o])[row] = h;
        }
        __syncthreads();

        // ---- D: query (O=256,K=256): 32 chunks CH=8 ----
        {
            gemv_task8(g_tWq, 256, s->ah2, 0, wid * 8, wid * 8 + 8,
                       s->part + (size_t)wid * 512);
            // prefetch pm for this warp's first score task
            int row = wid & 1, tt = wid >> 1;
            pf_raw(g_pmh + ((size_t)(b0 + row) * TENC + tt) * DMODEL + lane * 8);
        }
        __syncthreads();
        if (tid < 512) {
            int o = tid & 255, row = tid >> 8;
            s->qT[row][o] = redV8<32>(s->part, 0, o, row);
        }
        __syncthreads();

        // ---- E: Bahdanau scores (fp16 pm) ----
        {
            const float4* V = reinterpret_cast<const float4*>(s->v);
            float4 v0 = V[lane * 2], v1 = V[lane * 2 + 1];   // hoisted across tasks
            for (int task = wid; task < 2 * TENC; task += 32) {
                int row = task & 1, tt = task >> 1;
                const uint4* P = reinterpret_cast<const uint4*>(
                    g_pmh + ((size_t)(b0 + row) * TENC + tt) * DMODEL);
                uint4 pv = __ldg(&P[lane]);
                float2 p0 = __half22float2(*reinterpret_cast<__half2*>(&pv.x));
                float2 p1 = __half22float2(*reinterpret_cast<__half2*>(&pv.y));
                float2 p2 = __half22float2(*reinterpret_cast<__half2*>(&pv.z));
                float2 p3 = __half22float2(*reinterpret_cast<__half2*>(&pv.w));
                const float4* Q = reinterpret_cast<const float4*>(s->qT[row]);
                float4 q0 = Q[lane * 2], q1 = Q[lane * 2 + 1];
                float acc = 0.f;
                acc += v0.x * tanh_approx(p0.x + q0.x);
                acc += v0.y * tanh_approx(p0.y + q0.y);
                acc += v0.z * tanh_approx(p1.x + q0.z);
                acc += v0.w * tanh_approx(p1.y + q0.w);
                acc += v1.x * tanh_approx(p2.x + q1.x);
                acc += v1.y * tanh_approx(p2.y + q1.y);
                acc += v1.z * tanh_approx(p3.x + q1.z);
                acc += v1.w * tanh_approx(p3.y + q1.w);
#pragma unroll
                for (int sh = 16; sh; sh >>= 1) acc += __shfl_xor_sync(0xffffffffu, acc, sh);
                if (lane == 0)
                    s->sc[row][tt] = (tt < s->len_s[row]) ? acc : -1e9f;
            }
            // prefetch enc for this thread's ctx slice (phase G)
            {
                int g = tid & 63, row = (tid >> 6) & 1, ts = tid >> 7;
                pf_raw(g_ench + (size_t)(b0 + row) * TENC * DMODEL +
                       (size_t)(ts * 25) * DMODEL + g * 4);
            }
        }
        __syncthreads();

        // ---- F: softmax per row (warps 0..1) + alignment output ----
        if (wid < 2) {
            int row = wid;
            float m = -1e30f;
            for (int i = lane; i < TENC; i += 32) m = fmaxf(m, s->sc[row][i]);
#pragma unroll
            for (int sh = 16; sh; sh >>= 1) m = fmaxf(m, __shfl_xor_sync(0xffffffffu, m, sh));
            float sum = 0.f;
            for (int i = lane; i < TENC; i += 32) {
                float e = __expf(s->sc[row][i] - m);
                s->sc[row][i] = e;
                sum += e;
            }
#pragma unroll
            for (int sh = 16; sh; sh >>= 1) sum += __shfl_xor_sync(0xffffffffu, sum, sh);
            float inv = 1.f / sum;
            float* ao = outAl + ((size_t)(b0 + row) * TD + t) * TENC;
            for (int i = lane; i < TENC; i += 32) {
                float a = s->sc[row][i] * inv;
                s->sc[row][i] = a;
                if (write_align) ao[i] = a;
            }
        }
        __syncthreads();

        // ---- G: attention context (fp16 enc): g(64) x row(2) x ts(8x25) ----
        {
            int g = tid & 63, row = (tid >> 6) & 1, ts = tid >> 7;
            const uint2* E = reinterpret_cast<const uint2*>(
                                 g_ench + (size_t)(b0 + row) * TENC * DMODEL);
            const float* scp = s->sc[row];
            float4 acc = make_float4(0.f, 0.f, 0.f, 0.f);
            int tt0 = ts * 25;
#pragma unroll 5
            for (int tt = tt0; tt < tt0 + 25; ++tt) {
                float a = scp[tt];
                uint2 ev = __ldg(&E[tt * 64 + g]);
                float2 e0 = __half22float2(*reinterpret_cast<__half2*>(&ev.x));
                float2 e1 = __half22float2(*reinterpret_cast<__half2*>(&ev.y));
                acc.x = fmaf(a, e0.x, acc.x);
                acc.y = fmaf(a, e0.y, acc.y);
                acc.z = fmaf(a, e1.x, acc.z);
                acc.w = fmaf(a, e1.y, acc.w);
            }
            reinterpret_cast<float4*>(s->part)[(ts * 2 + row) * 64 + g] = acc;
            pfw(g_tWproj, 256, 0, wid * 16);           // prefetch H
        }
        __syncthreads();
        if (tid < 512) {
            int o = tid & 255, row = tid >> 8;
            int gg = o >> 2, comp = o & 3;
            const float* pf = s->part;
            float sv = 0.f;
#pragma unroll
            for (int ts = 0; ts < 8; ++ts)
                sv += pf[((ts * 2 + row) * 64 + gg) * 4 + comp];
            reinterpret_cast<float*>(&s->x2[128 + o])[row] = sv;
            reinterpret_cast<float*>(&s->cat2[256 + o])[row] = sv;
        }
        __syncthreads();

        // ---- H: proj (O=256,K=512): 32 chunks CH=16 ----
        {
            gemv_task8(g_tWproj, 256, s->cat2, 0, wid * 16, wid * 16 + 16,
                       s->part + (size_t)wid * 512);
            // prefetch decoder GRU1
            if (wid < 15) pfw(g_tWd1i, 768, (wid / 5) * 256, ((wid % 5) * 256) / 5);
            else if (wid < 30) { int t2 = wid - 15; pfw(g_tWd1h, 768, (t2 / 5) * 256, ((t2 % 5) * 256) / 5); }
        }
        __syncthreads();
        if (tid < 512) {
            int o = tid & 255, row = tid >> 8;
            float r = redV8<32>(s->part, 0, o, row) + s->b_proj[o];
            reinterpret_cast<float*>(&s->d2[o])[row] = r;
        }
        __syncthreads();

        // ---- I/J: decoder GRUs: gi 15 tasks (3x5) + gh 15 tasks (3x5) ----
#pragma unroll
        for (int gru = 0; gru < 2; ++gru) {
            const __half* Wi = gru ? g_tWd2i : g_tWd1i;
            const __half* Wh = gru ? g_tWd2h : g_tWd1h;
            const float* bi = gru ? s->b_d2i : s->b_d1i;
            const float* bh = gru ? s->b_d2h : s->b_d1h;
            float2* hstate = gru ? s->h22 : s->h12;
            for (int task = wid; task < 30; task += 32) {
                if (task < 15) {
                    int ot = task / 5, c = task - ot * 5;
                    gemv_task8(Wi, 768, s->d2, ot * 256,
                               (c * 256) / 5, ((c + 1) * 256) / 5,
                               s->part + (size_t)task * 512);
                } else {
                    int t2 = task - 15;
                    int ot = t2 / 5, c = t2 - ot * 5;
                    gemv_task8(Wh, 768, hstate, ot * 256,
                               (c * 256) / 5, ((c + 1) * 256) / 5,
                               s->part + (size_t)task * 512);
                }
            }
            // prefetch next phase's weights
            if (gru == 0) {
                if (wid < 15) pfw(g_tWd2i, 768, (wid / 5) * 256, ((wid % 5) * 256) / 5);
                else if (wid < 30) { int t2 = wid - 15; pfw(g_tWd2h, 768, (t2 / 5) * 256, ((t2 % 5) * 256) / 5); }
            } else {
                pfw(g_tWmel, 512, (wid >> 4) * 256, (wid & 15) * 16);
            }
            __syncthreads();
            if (tid < 512) {
                int o = tid & 255, row = tid >> 8;
                float ir = redV8<5>(s->part, 0, o, row) + bi[o];
                float iz = redV8<5>(s->part, 0, 256 + o, row) + bi[256 + o];
                float in = redV8<5>(s->part, 0, 512 + o, row) + bi[512 + o];
                float hr = redV8<5>(s->part, 15, o, row) + bh[o];
                float hz = redV8<5>(s->part, 15, 256 + o, row) + bh[256 + o];
                float hn = redV8<5>(s->part, 15, 512 + o, row) + bh[512 + o];
                float hp = reinterpret_cast<float*>(&hstate[o])[row];
                float rg = sigmoidf_(ir + hr);
                float z = sigmoidf_(iz + hz);
                float n = tanhf(in + rg * hn);
                float h = (1.f - z) * n + z * hp;
                reinterpret_cast<float*>(&hstate[o])[row] = h;
                reinterpret_cast<float*>(&s->d2[o])[row] += h;
            }
            __syncthreads();
        }

        // ---- K: mel (O=512 pad, K=256): 2 tiles x 16 chunks CH=16 ----
        {
            int ot = wid >> 4, c = wid & 15;
            gemv_task8(g_tWmel, 512, s->d2, ot * 256, c * 16, c * 16 + 16,
                       s->part + (size_t)wid * 512);
            pfw(g_tWp1, 256, 0, (wid * 25) >> 1);      // prefetch next-step A
        }
        __syncthreads();
        if (tid < 2 * INR) {
            int row = tid / INR, o = tid - row * INR;
            float r = redV8<16>(s->part, 0, o, row) + s->b_mel[o];
            outMel[((size_t)(b0 + row) * TD + t) * INR + o] = r;
        }
        __syncthreads();
    }
}

// ------------------------- launch -------------------------
extern "C" void kernel_launch(void* const* d_in, const int* in_sizes, int n_in,
                              void* d_out, int out_size) {
    const float* enc = (const float*)d_in[0];
    const float* inputs = (const float*)d_in[1];
    const int* memlen = (const int*)d_in[2];

    PrepArgs a;
    static const int srcIdx[11] = {3, 5, 7, 9, 12, 14, 16, 18, 20, 22, 24};
    static const int Oarr[11] = {256, 128, 768, 768, 256, 256, 768, 768, 768, 768, 400};
    static const int Karr[11] = {400, 256, 384, 256, 256, 512, 256, 256, 256, 256, 256};
    static const int OParr[11] = {256, 128, 768, 768, 256, 256, 768, 768, 768, 768, 512};

    void* dsts[11];
    cudaGetSymbolAddress(&dsts[0], g_tWp1);
    cudaGetSymbolAddress(&dsts[1], g_tWp2);
    cudaGetSymbolAddress(&dsts[2], g_tWaih);
    cudaGetSymbolAddress(&dsts[3], g_tWahh);
    cudaGetSymbolAddress(&dsts[4], g_tWq);
    cudaGetSymbolAddress(&dsts[5], g_tWproj);
    cudaGetSymbolAddress(&dsts[6], g_tWd1i);
    cudaGetSymbolAddress(&dsts[7], g_tWd1h);
    cudaGetSymbolAddress(&dsts[8], g_tWd2i);
    cudaGetSymbolAddress(&dsts[9], g_tWd2h);
    cudaGetSymbolAddress(&dsts[10], g_tWmel);

    int cum = 0;
    for (int m = 0; m < 11; ++m) {
        a.src[m] = (const float*)d_in[srcIdx[m]];
        a.dst[m] = (__half*)dsts[m];
        a.O[m] = Oarr[m]; a.K[m] = Karr[m]; a.OP[m] = OParr[m];
        a.start[m] = cum;
        cum += (Karr[m] * OParr[m]) / PREP_TB;
    }
    a.start[11] = cum;   // 6800
    a.enc = enc;
    a.memW = (const float*)d_in[11];
    cudaGetSymbolAddress((void**)&a.pm, g_pmh);
    cudaGetSymbolAddress((void**)&a.ench, g_ench);

    prep_kernel<<<PM_BLOCKS + cum + ENC_CVT_BLOCKS, PREP_TB>>>(a);

    static bool attr_done = false;
    if (!attr_done) {
        cudaFuncSetAttribute(decoder_kernel,
                             cudaFuncAttributeMaxDynamicSharedMemorySize,
                             (int)sizeof(SD));
        attr_done = true;
    }

    int write_align = (out_size >= BATCH * TD * (INR + TENC)) ? 1 : 0;

    decoder_kernel<<<NGROUPS, TB, sizeof(SD)>>>(
        inputs, memlen,
        (const float*)d_in[4], (const float*)d_in[6],
        (const float*)d_in[8], (const float*)d_in[10],
        (const float*)d_in[13],
        (const float*)d_in[15],
        (const float*)d_in[17], (const float*)d_in[19],
        (const float*)d_in[21], (const float*)d_in[23],
        (const float*)d_in[25],
        (float*)d_out, write_align);
}